// round 12
// baseline (speedup 1.0000x reference)
#include <cuda_runtime.h>
#include <cuda_fp16.h>
#include <math.h>
#include <stdint.h>

#define C_DIM   1024
#define H_NUM   16
#define DH      64
#define FF_DIM  4096
#define B_NUM   2
#define T_LEN   2048
#define M_TOK   4096   // B*T

// ---------------- scratch (device globals; no allocation allowed) ----------
__device__ __half g_h16 [M_TOK * C_DIM];       // rmsnorm out (fp16)
__device__ float  g_qkv [M_TOK * 3 * C_DIM];
__device__ __half g_q16 [M_TOK * C_DIM];       // [B,H,T,dh] (pre-scaled fp16)
__device__ __half g_k16 [M_TOK * C_DIM];       // [B,H,T,dh] fp16
__device__ __half g_v16 [M_TOK * C_DIM];       // [B,H,dh,T] fp16 (transposed)
__device__ __half g_o16 [M_TOK * C_DIM];       // attention out (fp16)
__device__ float  g_x1  [M_TOK * C_DIM];
__device__ float  g_ff  [M_TOK * FF_DIM];      // a = h2 @ w1^T (fp32)
__device__ __half g_ff16[M_TOK * FF_DIM];      // silu(a)*b (fp16)
__device__ __half g_w16 [16 * C_DIM * C_DIM];  // all weights fp16 (16M halves)

// ---------------- helpers ----------------------------------------------------
__device__ __forceinline__ void mma_f16(float c[4],
                                        uint32_t a0, uint32_t a1, uint32_t a2, uint32_t a3,
                                        uint32_t b0, uint32_t b1) {
    asm volatile(
        "mma.sync.aligned.m16n8k16.row.col.f32.f16.f16.f32 "
        "{%0,%1,%2,%3}, {%4,%5,%6,%7}, {%8,%9}, {%0,%1,%2,%3};\n"
        : "+f"(c[0]), "+f"(c[1]), "+f"(c[2]), "+f"(c[3])
        : "r"(a0), "r"(a1), "r"(a2), "r"(a3), "r"(b0), "r"(b1));
}
__device__ __forceinline__ void ldsm4(uint32_t& r0, uint32_t& r1,
                                      uint32_t& r2, uint32_t& r3, uint32_t addr) {
    asm volatile("ldmatrix.sync.aligned.m8n8.x4.shared.b16 {%0,%1,%2,%3}, [%4];"
                 : "=r"(r0), "=r"(r1), "=r"(r2), "=r"(r3) : "r"(addr));
}
__device__ __forceinline__ void cp16(uint32_t dst, const void* src) {
    asm volatile("cp.async.cg.shared.global [%0], [%1], 16;" :: "r"(dst), "l"(src));
}

// ---------------- fused fp32 -> fp16 weight convert (single launch) ---------
// 16M elems; block = 8192 contiguous elems; blockIdx>>7 = 1M-elem unit 0..15.
__global__ void f2h_all_kernel(const float* __restrict__ w_qkv,
                               const float* __restrict__ w_proj,
                               const float* __restrict__ w1,
                               const float* __restrict__ w2,
                               const float* __restrict__ w3,
                               __half* __restrict__ out) {
    int unit = blockIdx.x >> 7;
    const float* src;
    if (unit < 3)       src = w_qkv  + ((size_t)unit << 20);
    else if (unit < 4)  src = w_proj;
    else if (unit < 8)  src = w1 + ((size_t)(unit - 4) << 20);
    else if (unit < 12) src = w2 + ((size_t)(unit - 8) << 20);
    else                src = w3 + ((size_t)(unit - 12) << 20);
    __half* dst = out + ((size_t)unit << 20);

    size_t local = (size_t)(blockIdx.x & 127) * 8192 + threadIdx.x * 8;
    #pragma unroll
    for (int j = 0; j < 4; j++) {
        size_t idx = local + (size_t)j * 2048;
        float4 a = *(const float4*)(src + idx);
        float4 b = *(const float4*)(src + idx + 4);
        __half2 h0 = __floats2half2_rn(a.x, a.y);
        __half2 h1 = __floats2half2_rn(a.z, a.w);
        __half2 h2 = __floats2half2_rn(b.x, b.y);
        __half2 h3 = __floats2half2_rn(b.z, b.w);
        uint4 u;
        u.x = *(uint32_t*)&h0; u.y = *(uint32_t*)&h1;
        u.z = *(uint32_t*)&h2; u.w = *(uint32_t*)&h3;
        *(uint4*)(dst + idx) = u;
    }
}

// ---------------- RMSNorm -> fp16 --------------------------------------------
__global__ void rmsnorm_h_kernel(const float* __restrict__ x,
                                 const float* __restrict__ g,
                                 __half* __restrict__ y) {
    int row = blockIdx.x;
    int tid = threadIdx.x;
    const float4* xr = (const float4*)(x + (size_t)row * C_DIM);
    const float4* gr = (const float4*)g;

    float4 xv = xr[tid];
    float ss = xv.x*xv.x + xv.y*xv.y + xv.z*xv.z + xv.w*xv.w;
    #pragma unroll
    for (int off = 16; off > 0; off >>= 1)
        ss += __shfl_xor_sync(0xffffffffu, ss, off);
    __shared__ float red[8];
    if ((tid & 31) == 0) red[tid >> 5] = ss;
    __syncthreads();
    float tot = 0.f;
    #pragma unroll
    for (int i = 0; i < 8; i++) tot += red[i];
    float inv = rsqrtf(tot * (1.0f / C_DIM) + 1e-5f);

    float4 gv = gr[tid];
    __half2 h0 = __floats2half2_rn(xv.x * gv.x * inv, xv.y * gv.y * inv);
    __half2 h1 = __floats2half2_rn(xv.z * gv.z * inv, xv.w * gv.w * inv);
    uint2 u;
    u.x = *(uint32_t*)&h0; u.y = *(uint32_t*)&h1;
    *(uint2*)(y + (size_t)row * C_DIM + tid * 4) = u;
}

// ---------------- fp16 tensor-core GEMM: C[M,N] = A[M,K] @ W[N,K]^T ---------
// Block 128x128, k32 iterations, 4-stage cp.async pipeline (wait_group 2).
// Stage = 128 rows x 32 halves (64B rows; swizzle u ^= (row>>1)&3).
// MODE 0: fp32 out  MODE 1: fp32 out + X residual  MODE 2: fp16 out, silu(X)*acc
#define GST 4
template <int MODE>
__global__ __launch_bounds__(256, 2)
void hgemm_kernel(const __half* __restrict__ A, const __half* __restrict__ W,
                  const float* X, void* Cout, int M, int N, int K) {
    __shared__ __align__(16) __half sA[GST][128 * 32];
    __shared__ __align__(16) __half sB[GST][128 * 32];

    int tid  = threadIdx.x;
    int bm   = blockIdx.y * 128;
    int bn   = blockIdx.x * 128;
    int warp = tid >> 5;
    int lane = tid & 31;
    int wm   = (warp >> 1) * 32;
    int wn   = (warp & 1) * 64;

    uint32_t dstOff[2];
    int srow[2], su[2];
    #pragma unroll
    for (int j = 0; j < 2; j++) {
        int idx = tid + 256 * j;
        int row = idx >> 2, u = idx & 3;
        int uz  = u ^ ((row >> 1) & 3);
        dstOff[j] = (uint32_t)(row * 32 + uz * 8) * 2u;
        srow[j] = row; su[j] = u;
    }

    uint32_t aBase = (uint32_t)__cvta_generic_to_shared(&sA[0][0]);
    uint32_t bBase = (uint32_t)__cvta_generic_to_shared(&sB[0][0]);

    int l15 = lane & 15, lh = lane >> 4;
    uint32_t offA[2][2];
    #pragma unroll
    for (int q = 0; q < 2; q++)
        #pragma unroll
        for (int mt = 0; mt < 2; mt++) {
            int row = wm + mt * 16 + l15;
            int u   = 2 * q + lh;
            int uz  = u ^ ((row >> 1) & 3);
            offA[q][mt] = (uint32_t)(row * 32 + uz * 8) * 2u;
        }
    uint32_t offB[2][2][2];
    #pragma unroll
    for (int q = 0; q < 2; q++)
        #pragma unroll
        for (int kh = 0; kh < 2; kh++)
            #pragma unroll
            for (int gb = 0; gb < 2; gb++) {
                int row = wn + gb * 32 + lane;
                int u   = 2 * q + kh;
                int uz  = u ^ ((row >> 1) & 3);
                offB[q][kh][gb] = (uint32_t)(row * 32 + uz * 8) * 2u;
            }

    float acc[2][8][4];
    #pragma unroll
    for (int mt = 0; mt < 2; mt++)
        #pragma unroll
        for (int nt = 0; nt < 8; nt++)
            #pragma unroll
            for (int e = 0; e < 4; e++) acc[mt][nt][e] = 0.f;

    int NC = K >> 5;

    // prologue: stages 0..2 in flight
    #pragma unroll
    for (int s = 0; s < GST - 1; s++) {
        #pragma unroll
        for (int j = 0; j < 2; j++) {
            cp16(aBase + s * 8192u + dstOff[j],
                 A + (size_t)(bm + srow[j]) * K + s * 32 + su[j] * 8);
            cp16(bBase + s * 8192u + dstOff[j],
                 W + (size_t)(bn + srow[j]) * K + s * 32 + su[j] * 8);
        }
        asm volatile("cp.async.commit_group;" ::: "memory");
    }

    int st = 0, sn = GST - 1;
    for (int ck = 0; ck < NC; ck++) {
        asm volatile("cp.async.wait_group %0;" :: "n"(GST - 2) : "memory");
        __syncthreads();

        uint32_t tA = aBase + st * 8192u;
        uint32_t tB = bBase + st * 8192u;
        #pragma unroll
        for (int q = 0; q < 2; q++) {
            uint32_t aR[2][4], bR[2][2][4];
            ldsm4(aR[0][0], aR[0][1], aR[0][2], aR[0][3], tA + offA[q][0]);
            ldsm4(aR[1][0], aR[1][1], aR[1][2], aR[1][3], tA + offA[q][1]);
            #pragma unroll
            for (int kh = 0; kh < 2; kh++)
                #pragma unroll
                for (int gb = 0; gb < 2; gb++)
                    ldsm4(bR[kh][gb][0], bR[kh][gb][1], bR[kh][gb][2], bR[kh][gb][3],
                          tB + offB[q][kh][gb]);
            #pragma unroll
            for (int mt = 0; mt < 2; mt++)
                #pragma unroll
                for (int nt = 0; nt < 8; nt++)
                    mma_f16(acc[mt][nt],
                            aR[mt][0], aR[mt][1], aR[mt][2], aR[mt][3],
                            bR[0][nt >> 2][nt & 3], bR[1][nt >> 2][nt & 3]);
        }

        int cn = ck + GST - 1;
        if (cn < NC) {
            uint32_t nA = aBase + sn * 8192u;
            uint32_t nB = bBase + sn * 8192u;
            #pragma unroll
            for (int j = 0; j < 2; j++) {
                cp16(nA + dstOff[j],
                     A + (size_t)(bm + srow[j]) * K + cn * 32 + su[j] * 8);
                cp16(nB + dstOff[j],
                     W + (size_t)(bn + srow[j]) * K + cn * 32 + su[j] * 8);
            }
        }
        asm volatile("cp.async.commit_group;" ::: "memory");

        st = (st + 1 == GST) ? 0 : st + 1;
        sn = (sn + 1 == GST) ? 0 : sn + 1;
    }

    // epilogue
    int g = lane >> 2;
    int t = lane & 3;
    #pragma unroll
    for (int mt = 0; mt < 2; mt++) {
        #pragma unroll
        for (int half = 0; half < 2; half++) {
            int row = bm + wm + mt * 16 + half * 8 + g;
            const float* xrow = (MODE != 0) ? (X + (size_t)row * N) : nullptr;
            #pragma unroll
            for (int nt = 0; nt < 8; nt++) {
                int col = bn + wn + nt * 8 + 2 * t;
                float2 v;
                v.x = acc[mt][nt][half * 2 + 0];
                v.y = acc[mt][nt][half * 2 + 1];
                if (MODE == 1) {
                    float2 xv = *(const float2*)(xrow + col);
                    v.x += xv.x; v.y += xv.y;
                }
                if (MODE == 2) {
                    float2 xv = *(const float2*)(xrow + col);
                    v.x *= xv.x / (1.f + expf(-xv.x));
                    v.y *= xv.y / (1.f + expf(-xv.y));
                }
                if (MODE == 2) {
                    __half2 hv = __floats2half2_rn(v.x, v.y);
                    *(uint32_t*)((__half*)Cout + (size_t)row * N + col) =
                        *(uint32_t*)&hv;
                } else {
                    *(float2*)((float*)Cout + (size_t)row * N + col) = v;
                }
            }
        }
    }
}

// ---------------- RoPE + split qkv -> q,k fp16 [B,H,T,dh] -------------------
#define Q_SCALE (0.125f * 1.44269504088896f)   // 1/sqrt(64) * log2(e)
__global__ void rope_split_h_kernel(const float* __restrict__ qkv,
                                    __half* __restrict__ q,
                                    __half* __restrict__ k) {
    int idx = blockIdx.x * blockDim.x + threadIdx.x;
    int i = idx & 31;
    int h = (idx >> 5) & 15;
    int m = idx >> 9;
    int b = m >> 11;
    int t = m & 2047;

    const float* base = qkv + (size_t)m * (3 * C_DIM) + h * DH + 2 * i;
    float q1 = base[0],     q2 = base[1];
    float k1 = base[C_DIM], k2 = base[C_DIM + 1];

    float freq = expf(-(2.0f * (float)i) * (1.0f / 64.0f) * 9.210340371976184f);
    float th = (float)t * freq;
    float s, c;
    sincosf(th, &s, &c);

    size_t o = ((size_t)(b * H_NUM + h) * T_LEN + t) * DH + 2 * i;
    __half2 qh = __floats2half2_rn((q1 * c - q2 * s) * Q_SCALE,
                                   (q1 * s + q2 * c) * Q_SCALE);
    __half2 kh = __floats2half2_rn(k1 * c - k2 * s, k1 * s + k2 * c);
    *(uint32_t*)(q + o) = *(uint32_t*)&qh;
    *(uint32_t*)(k + o) = *(uint32_t*)&kh;
}

// ---------------- V transpose: qkv v-section -> [B,H,dh,T] fp16 -------------
__global__ void vtrans_h_kernel(const float* __restrict__ qkv,
                                __half* __restrict__ vt) {
    __shared__ float s[64][65];
    int bh = blockIdx.y;
    int b  = bh >> 4;
    int h  = bh & 15;
    int t0 = blockIdx.x * 64;
    int tid = threadIdx.x;

    for (int idx = tid; idx < 64 * 64; idx += 256) {
        int tok = idx >> 6, d = idx & 63;
        s[tok][d] = qkv[(size_t)(b * T_LEN + t0 + tok) * (3 * C_DIM)
                        + 2 * C_DIM + h * DH + d];
    }
    __syncthreads();
    for (int idx = tid; idx < 64 * 32; idx += 256) {
        int d = idx >> 5, tp = idx & 31;
        __half2 hv = __floats2half2_rn(s[2 * tp][d], s[2 * tp + 1][d]);
        *(uint32_t*)(vt + ((size_t)bh * DH + d) * T_LEN + t0 + 2 * tp) =
            *(uint32_t*)&hv;
    }
}

// ---------------- fp16 causal flash attention, 128-query blocks -------------
// grid (T/128, B*H), 256 threads (8 warps x 16 query rows).
#define HPAD 72
#define ONES16 0x3C003C00u
__global__ __launch_bounds__(256)
void attn_h_kernel(const __half* __restrict__ Q,
                   const __half* __restrict__ Kg,
                   const __half* __restrict__ Vt,
                   __half* __restrict__ O) {
    __shared__ __align__(16) __half sQ[128 * HPAD];   // later: P (128 rows)
    __shared__ __align__(16) __half sK[64 * HPAD];
    __shared__ __align__(16) __half sV[64 * HPAD];

    int bh   = blockIdx.y;
    int b    = bh >> 4;
    int head = bh & 15;
    int q0   = blockIdx.x * 128;
    int tid  = threadIdx.x;
    int warp = tid >> 5;
    int lane = tid & 31;
    int wm   = warp * 16;            // 0..112
    int g    = lane >> 2;
    int t    = lane & 3;
    int l15  = lane & 15;
    int lh   = lane >> 4;

    uint32_t qB = (uint32_t)__cvta_generic_to_shared(sQ);
    uint32_t kB = (uint32_t)__cvta_generic_to_shared(sK);
    uint32_t vB = (uint32_t)__cvta_generic_to_shared(sV);

    // load Q tile (128 x 64 halves = 1024 16B units)
    const __half* qg = Q + ((size_t)bh * T_LEN + q0) * DH;
    #pragma unroll
    for (int idx = tid; idx < 1024; idx += 256) {
        int r = idx >> 3, u = idx & 7;
        *(uint4*)&sQ[r * HPAD + u * 8] = *(const uint4*)(qg + r * DH + u * 8);
    }
    __syncthreads();

    uint32_t qf[4][4];
    #pragma unroll
    for (int kc = 0; kc < 4; kc++) {
        int row = wm + l15;
        int u   = kc * 2 + lh;
        ldsm4(qf[kc][0], qf[kc][1], qf[kc][2], qf[kc][3],
              qB + (uint32_t)(row * HPAD + u * 8) * 2u);
    }
    __syncthreads();   // sQ now reusable as P

    float accO[8][4];
    #pragma unroll
    for (int nt = 0; nt < 8; nt++)
        #pragma unroll
        for (int e = 0; e < 4; e++) accO[nt][e] = 0.f;
    float lacc[4] = {0.f, 0.f, 0.f, 0.f};
    float m0 = -1e30f, m1 = -1e30f;

    int r0 = q0 + wm + g;
    int r1 = r0 + 8;
    int prow0 = (wm + g) * HPAD;
    int prow1 = (wm + g + 8) * HPAD;

    int ntiles = q0 / 64 + 2;        // covers keys up to q0+127
    for (int kt = 0; kt < ntiles; kt++) {
        int ks = kt * 64;
        const __half* kbase = Kg + ((size_t)bh * T_LEN + ks) * DH;
        const __half* vbase = Vt + (size_t)bh * DH * T_LEN + ks;
        #pragma unroll
        for (int idx = tid; idx < 512; idx += 256) {
            int r = idx >> 3, u = idx & 7;
            *(uint4*)&sK[r * HPAD + u * 8] = *(const uint4*)(kbase + r * DH + u * 8);
            *(uint4*)&sV[r * HPAD + u * 8] =
                *(const uint4*)(vbase + (size_t)r * T_LEN + u * 8);
        }
        __syncthreads();

        if (ks <= q0 + wm + 15) {
            // ---- S = Q @ K^T ----
            float s[8][4];
            #pragma unroll
            for (int nt = 0; nt < 8; nt++)
                #pragma unroll
                for (int e = 0; e < 4; e++) s[nt][e] = 0.f;

            #pragma unroll
            for (int kc = 0; kc < 4; kc++) {
                uint32_t bR[2][2][4];
                #pragma unroll
                for (int kh = 0; kh < 2; kh++)
                    #pragma unroll
                    for (int gb = 0; gb < 2; gb++) {
                        int row = gb * 32 + lane;
                        int u   = kc * 2 + kh;
                        ldsm4(bR[kh][gb][0], bR[kh][gb][1],
                              bR[kh][gb][2], bR[kh][gb][3],
                              kB + (uint32_t)(row * HPAD + u * 8) * 2u);
                    }
                #pragma unroll
                for (int nt = 0; nt < 8; nt++)
                    mma_f16(s[nt], qf[kc][0], qf[kc][1], qf[kc][2], qf[kc][3],
                            bR[0][nt >> 2][nt & 3], bR[1][nt >> 2][nt & 3]);
            }

            // ---- causal mask ----
            if (ks + 63 > q0 + wm) {
                #pragma unroll
                for (int nt = 0; nt < 8; nt++) {
                    int kc = ks + nt * 8 + 2 * t;
                    if (kc     > r0) s[nt][0] = -1e30f;
                    if (kc + 1 > r0) s[nt][1] = -1e30f;
                    if (kc     > r1) s[nt][2] = -1e30f;
                    if (kc + 1 > r1) s[nt][3] = -1e30f;
                }
            }

            // ---- online softmax (log2 domain; f16x2 approx exp) ----
            float tm0 = -1e30f, tm1 = -1e30f;
            #pragma unroll
            for (int nt = 0; nt < 8; nt++) {
                tm0 = fmaxf(tm0, fmaxf(s[nt][0], s[nt][1]));
                tm1 = fmaxf(tm1, fmaxf(s[nt][2], s[nt][3]));
            }
            tm0 = fmaxf(tm0, __shfl_xor_sync(0xffffffffu, tm0, 1));
            tm0 = fmaxf(tm0, __shfl_xor_sync(0xffffffffu, tm0, 2));
            tm1 = fmaxf(tm1, __shfl_xor_sync(0xffffffffu, tm1, 1));
            tm1 = fmaxf(tm1, __shfl_xor_sync(0xffffffffu, tm1, 2));

            float mn0 = fmaxf(m0, tm0), mn1 = fmaxf(m1, tm1);
            float c0 = exp2f(m0 - mn0), c1 = exp2f(m1 - mn1);
            m0 = mn0; m1 = mn1;

            #pragma unroll
            for (int nt = 0; nt < 8; nt++) {
                uint32_t ha, hb;
                asm("cvt.rn.f16x2.f32 %0, %1, %2;" : "=r"(ha)
                    : "f"(s[nt][1] - mn0), "f"(s[nt][0] - mn0));
                asm("cvt.rn.f16x2.f32 %0, %1, %2;" : "=r"(hb)
                    : "f"(s[nt][3] - mn1), "f"(s[nt][2] - mn1));
                asm("ex2.approx.f16x2 %0, %1;" : "=r"(ha) : "r"(ha));
                asm("ex2.approx.f16x2 %0, %1;" : "=r"(hb) : "r"(hb));
                int col = nt * 8 + 2 * t;
                *(uint32_t*)&sQ[prow0 + col] = ha;
                *(uint32_t*)&sQ[prow1 + col] = hb;
            }

            #pragma unroll
            for (int nt = 0; nt < 8; nt++) {
                accO[nt][0] *= c0; accO[nt][1] *= c0;
                accO[nt][2] *= c1; accO[nt][3] *= c1;
            }
            lacc[0] *= c0; lacc[1] *= c0;
            lacc[2] *= c1; lacc[3] *= c1;
            __syncwarp();

            // ---- O += P @ V ; l += P @ 1 ----
            #pragma unroll
            for (int kc = 0; kc < 4; kc++) {
                uint32_t aP[4];
                {
                    int row = wm + l15;
                    int u   = kc * 2 + lh;
                    ldsm4(aP[0], aP[1], aP[2], aP[3],
                          qB + (uint32_t)(row * HPAD + u * 8) * 2u);
                }
                mma_f16(lacc, aP[0], aP[1], aP[2], aP[3], ONES16, ONES16);
                uint32_t bV[2][2][4];
                #pragma unroll
                for (int kh = 0; kh < 2; kh++)
                    #pragma unroll
                    for (int gb = 0; gb < 2; gb++) {
                        int row = gb * 32 + lane;
                        int u   = kc * 2 + kh;
                        ldsm4(bV[kh][gb][0], bV[kh][gb][1],
                              bV[kh][gb][2], bV[kh][gb][3],
                              vB + (uint32_t)(row * HPAD + u * 8) * 2u);
                    }
                #pragma unroll
                for (int nt = 0; nt < 8; nt++)
                    mma_f16(accO[nt], aP[0], aP[1], aP[2], aP[3],
                            bV[0][nt >> 2][nt & 3], bV[1][nt >> 2][nt & 3]);
            }
        }
        __syncthreads();
    }

    // ---- epilogue (fp16 out) ----
    float inv0 = 1.f / lacc[0], inv1 = 1.f / lacc[2];
    __half* o0 = O + ((size_t)(b * T_LEN + r0)) * C_DIM + head * DH;
    __half* o1 = O + ((size_t)(b * T_LEN + r1)) * C_DIM + head * DH;
    #pragma unroll
    for (int nt = 0; nt < 8; nt++) {
        int col = nt * 8 + 2 * t;
        __half2 h0 = __floats2half2_rn(accO[nt][0] * inv0, accO[nt][1] * inv0);
        __half2 h1 = __floats2half2_rn(accO[nt][2] * inv1, accO[nt][3] * inv1);
        *(uint32_t*)(o0 + col) = *(uint32_t*)&h0;
        *(uint32_t*)(o1 + col) = *(uint32_t*)&h1;
    }
}

// ---------------- launch ----------------------------------------------------
extern "C" void kernel_launch(void* const* d_in, const int* in_sizes, int n_in,
                              void* d_out, int out_size) {
    const float* x      = (const float*)d_in[0];
    const float* w_qkv  = (const float*)d_in[1];
    const float* w_proj = (const float*)d_in[2];
    const float* g1     = (const float*)d_in[3];
    const float* g2     = (const float*)d_in[4];
    const float* w1     = (const float*)d_in[5];
    const float* w2     = (const float*)d_in[6];
    const float* w3     = (const float*)d_in[7];
    float* out = (float*)d_out;

    __half *p_h16, *p_q16, *p_k16, *p_v16, *p_o16, *p_ff16, *p_w16;
    float  *p_qkv, *p_x1, *p_ff;
    cudaGetSymbolAddress((void**)&p_h16,  g_h16);
    cudaGetSymbolAddress((void**)&p_qkv,  g_qkv);
    cudaGetSymbolAddress((void**)&p_q16,  g_q16);
    cudaGetSymbolAddress((void**)&p_k16,  g_k16);
    cudaGetSymbolAddress((void**)&p_v16,  g_v16);
    cudaGetSymbolAddress((void**)&p_o16,  g_o16);
    cudaGetSymbolAddress((void**)&p_x1,   g_x1);
    cudaGetSymbolAddress((void**)&p_ff,   g_ff);
    cudaGetSymbolAddress((void**)&p_ff16, g_ff16);
    cudaGetSymbolAddress((void**)&p_w16,  g_w16);

    __half* w_qkv16  = p_w16;
    __half* w_proj16 = w_qkv16  + 3 * C_DIM * C_DIM;
    __half* w116     = w_proj16 + C_DIM * C_DIM;
    __half* w216     = w116     + 4 * C_DIM * C_DIM;
    __half* w316     = w216     + 4 * C_DIM * C_DIM;

    // single fused weight conversion
    f2h_all_kernel<<<2048, 256>>>(w_qkv, w_proj, w1, w2, w3, p_w16);

    rmsnorm_h_kernel<<<M_TOK, 256>>>(x, g1, p_h16);
    hgemm_kernel<0><<<dim3(3 * C_DIM / 128, M_TOK / 128), 256>>>(
        p_h16, w_qkv16, nullptr, p_qkv, M_TOK, 3 * C_DIM, C_DIM);
    rope_split_h_kernel<<<(M_TOK * H_NUM * 32) / 256, 256>>>(p_qkv, p_q16, p_k16);
    vtrans_h_kernel<<<dim3(T_LEN / 64, B_NUM * H_NUM), 256>>>(p_qkv, p_v16);
    attn_h_kernel<<<dim3(T_LEN / 128, B_NUM * H_NUM), 256>>>(
        p_q16, p_k16, p_v16, p_o16);
    hgemm_kernel<1><<<dim3(C_DIM / 128, M_TOK / 128), 256>>>(
        p_o16, w_proj16, x, p_x1, M_TOK, C_DIM, C_DIM);
    rmsnorm_h_kernel<<<M_TOK, 256>>>(p_x1, g2, p_h16);
    hgemm_kernel<0><<<dim3(FF_DIM / 128, M_TOK / 128), 256>>>(
        p_h16, w116, nullptr, p_ff, M_TOK, FF_DIM, C_DIM);
    hgemm_kernel<2><<<dim3(FF_DIM / 128, M_TOK / 128), 256>>>(
        p_h16, w316, p_ff, p_ff16, M_TOK, FF_DIM, C_DIM);
    hgemm_kernel<1><<<dim3(C_DIM / 128, M_TOK / 128), 256>>>(
        p_ff16, w216, p_x1, out, M_TOK, C_DIM, FF_DIM);
}

// round 13
// speedup vs baseline: 1.0283x; 1.0283x over previous
#include <cuda_runtime.h>
#include <cuda_fp16.h>
#include <math.h>
#include <stdint.h>

#define C_DIM   1024
#define H_NUM   16
#define DH      64
#define FF_DIM  4096
#define B_NUM   2
#define T_LEN   2048
#define M_TOK   4096   // B*T

// ---------------- scratch (device globals; no allocation allowed) ----------
__device__ __half g_h16 [M_TOK * C_DIM];       // rmsnorm out (fp16)
__device__ float  g_qkv [M_TOK * 3 * C_DIM];
__device__ __half g_q16 [M_TOK * C_DIM];       // [B,H,T,dh] (pre-scaled fp16)
__device__ __half g_k16 [M_TOK * C_DIM];       // [B,H,T,dh] fp16
__device__ __half g_v16 [M_TOK * C_DIM];       // [B,H,dh,T] fp16 (transposed)
__device__ __half g_o16 [M_TOK * C_DIM];       // attention out (fp16)
__device__ float  g_x1  [M_TOK * C_DIM];
__device__ float  g_ff  [M_TOK * FF_DIM];      // a = h2 @ w1^T (fp32)
__device__ __half g_ff16[M_TOK * FF_DIM];      // silu(a)*b (fp16)
__device__ __half g_w16 [16 * C_DIM * C_DIM];  // all weights fp16 (16M halves)

// ---------------- helpers ----------------------------------------------------
__device__ __forceinline__ void mma_f16(float c[4],
                                        uint32_t a0, uint32_t a1, uint32_t a2, uint32_t a3,
                                        uint32_t b0, uint32_t b1) {
    asm volatile(
        "mma.sync.aligned.m16n8k16.row.col.f32.f16.f16.f32 "
        "{%0,%1,%2,%3}, {%4,%5,%6,%7}, {%8,%9}, {%0,%1,%2,%3};\n"
        : "+f"(c[0]), "+f"(c[1]), "+f"(c[2]), "+f"(c[3])
        : "r"(a0), "r"(a1), "r"(a2), "r"(a3), "r"(b0), "r"(b1));
}
__device__ __forceinline__ void ldsm4(uint32_t& r0, uint32_t& r1,
                                      uint32_t& r2, uint32_t& r3, uint32_t addr) {
    asm volatile("ldmatrix.sync.aligned.m8n8.x4.shared.b16 {%0,%1,%2,%3}, [%4];"
                 : "=r"(r0), "=r"(r1), "=r"(r2), "=r"(r3) : "r"(addr));
}
__device__ __forceinline__ void cp16(uint32_t dst, const void* src) {
    asm volatile("cp.async.cg.shared.global [%0], [%1], 16;" :: "r"(dst), "l"(src));
}

// ---------------- fused fp32 -> fp16 weight convert (single launch) ---------
__global__ void f2h_all_kernel(const float* __restrict__ w_qkv,
                               const float* __restrict__ w_proj,
                               const float* __restrict__ w1,
                               const float* __restrict__ w2,
                               const float* __restrict__ w3,
                               __half* __restrict__ out) {
    int unit = blockIdx.x >> 7;
    const float* src;
    if (unit < 3)       src = w_qkv  + ((size_t)unit << 20);
    else if (unit < 4)  src = w_proj;
    else if (unit < 8)  src = w1 + ((size_t)(unit - 4) << 20);
    else if (unit < 12) src = w2 + ((size_t)(unit - 8) << 20);
    else                src = w3 + ((size_t)(unit - 12) << 20);
    __half* dst = out + ((size_t)unit << 20);

    size_t local = (size_t)(blockIdx.x & 127) * 8192 + threadIdx.x * 8;
    #pragma unroll
    for (int j = 0; j < 4; j++) {
        size_t idx = local + (size_t)j * 2048;
        float4 a = *(const float4*)(src + idx);
        float4 b = *(const float4*)(src + idx + 4);
        __half2 h0 = __floats2half2_rn(a.x, a.y);
        __half2 h1 = __floats2half2_rn(a.z, a.w);
        __half2 h2 = __floats2half2_rn(b.x, b.y);
        __half2 h3 = __floats2half2_rn(b.z, b.w);
        uint4 u;
        u.x = *(uint32_t*)&h0; u.y = *(uint32_t*)&h1;
        u.z = *(uint32_t*)&h2; u.w = *(uint32_t*)&h3;
        *(uint4*)(dst + idx) = u;
    }
}

// ---------------- RMSNorm -> fp16 --------------------------------------------
__global__ void rmsnorm_h_kernel(const float* __restrict__ x,
                                 const float* __restrict__ g,
                                 __half* __restrict__ y) {
    int row = blockIdx.x;
    int tid = threadIdx.x;
    const float4* xr = (const float4*)(x + (size_t)row * C_DIM);
    const float4* gr = (const float4*)g;

    float4 xv = xr[tid];
    float ss = xv.x*xv.x + xv.y*xv.y + xv.z*xv.z + xv.w*xv.w;
    #pragma unroll
    for (int off = 16; off > 0; off >>= 1)
        ss += __shfl_xor_sync(0xffffffffu, ss, off);
    __shared__ float red[8];
    if ((tid & 31) == 0) red[tid >> 5] = ss;
    __syncthreads();
    float tot = 0.f;
    #pragma unroll
    for (int i = 0; i < 8; i++) tot += red[i];
    float inv = rsqrtf(tot * (1.0f / C_DIM) + 1e-5f);

    float4 gv = gr[tid];
    __half2 h0 = __floats2half2_rn(xv.x * gv.x * inv, xv.y * gv.y * inv);
    __half2 h1 = __floats2half2_rn(xv.z * gv.z * inv, xv.w * gv.w * inv);
    uint2 u;
    u.x = *(uint32_t*)&h0; u.y = *(uint32_t*)&h1;
    *(uint2*)(y + (size_t)row * C_DIM + tid * 4) = u;
}

// ---------------- fp16 tensor-core GEMM (R11 proven: k32, 3-stage) ----------
#define GST 3
template <int MODE>
__global__ __launch_bounds__(256, 2)
void hgemm_kernel(const __half* __restrict__ A, const __half* __restrict__ W,
                  const float* X, void* Cout, int M, int N, int K) {
    __shared__ __align__(16) __half sA[GST][128 * 32];
    __shared__ __align__(16) __half sB[GST][128 * 32];

    int tid  = threadIdx.x;
    int bm   = blockIdx.y * 128;
    int bn   = blockIdx.x * 128;
    int warp = tid >> 5;
    int lane = tid & 31;
    int wm   = (warp >> 1) * 32;
    int wn   = (warp & 1) * 64;

    uint32_t dstOff[2];
    int srow[2], su[2];
    #pragma unroll
    for (int j = 0; j < 2; j++) {
        int idx = tid + 256 * j;
        int row = idx >> 2, u = idx & 3;
        int uz  = u ^ ((row >> 1) & 3);
        dstOff[j] = (uint32_t)(row * 32 + uz * 8) * 2u;
        srow[j] = row; su[j] = u;
    }

    uint32_t aBase = (uint32_t)__cvta_generic_to_shared(&sA[0][0]);
    uint32_t bBase = (uint32_t)__cvta_generic_to_shared(&sB[0][0]);

    int l15 = lane & 15, lh = lane >> 4;
    uint32_t offA[2][2];
    #pragma unroll
    for (int q = 0; q < 2; q++)
        #pragma unroll
        for (int mt = 0; mt < 2; mt++) {
            int row = wm + mt * 16 + l15;
            int u   = 2 * q + lh;
            int uz  = u ^ ((row >> 1) & 3);
            offA[q][mt] = (uint32_t)(row * 32 + uz * 8) * 2u;
        }
    uint32_t offB[2][2][2];
    #pragma unroll
    for (int q = 0; q < 2; q++)
        #pragma unroll
        for (int kh = 0; kh < 2; kh++)
            #pragma unroll
            for (int gb = 0; gb < 2; gb++) {
                int row = wn + gb * 32 + lane;
                int u   = 2 * q + kh;
                int uz  = u ^ ((row >> 1) & 3);
                offB[q][kh][gb] = (uint32_t)(row * 32 + uz * 8) * 2u;
            }

    float acc[2][8][4];
    #pragma unroll
    for (int mt = 0; mt < 2; mt++)
        #pragma unroll
        for (int nt = 0; nt < 8; nt++)
            #pragma unroll
            for (int e = 0; e < 4; e++) acc[mt][nt][e] = 0.f;

    int NC = K >> 5;

    #pragma unroll
    for (int s = 0; s < 2; s++) {
        #pragma unroll
        for (int j = 0; j < 2; j++) {
            cp16(aBase + s * 8192u + dstOff[j],
                 A + (size_t)(bm + srow[j]) * K + s * 32 + su[j] * 8);
            cp16(bBase + s * 8192u + dstOff[j],
                 W + (size_t)(bn + srow[j]) * K + s * 32 + su[j] * 8);
        }
        asm volatile("cp.async.commit_group;" ::: "memory");
    }

    int st = 0, sn = 2;
    for (int ck = 0; ck < NC; ck++) {
        asm volatile("cp.async.wait_group 1;" ::: "memory");
        __syncthreads();

        uint32_t tA = aBase + st * 8192u;
        uint32_t tB = bBase + st * 8192u;
        #pragma unroll
        for (int q = 0; q < 2; q++) {
            uint32_t aR[2][4], bR[2][2][4];
            ldsm4(aR[0][0], aR[0][1], aR[0][2], aR[0][3], tA + offA[q][0]);
            ldsm4(aR[1][0], aR[1][1], aR[1][2], aR[1][3], tA + offA[q][1]);
            #pragma unroll
            for (int kh = 0; kh < 2; kh++)
                #pragma unroll
                for (int gb = 0; gb < 2; gb++)
                    ldsm4(bR[kh][gb][0], bR[kh][gb][1], bR[kh][gb][2], bR[kh][gb][3],
                          tB + offB[q][kh][gb]);
            #pragma unroll
            for (int mt = 0; mt < 2; mt++)
                #pragma unroll
                for (int nt = 0; nt < 8; nt++)
                    mma_f16(acc[mt][nt],
                            aR[mt][0], aR[mt][1], aR[mt][2], aR[mt][3],
                            bR[0][nt >> 2][nt & 3], bR[1][nt >> 2][nt & 3]);
        }

        int cn = ck + 2;
        if (cn < NC) {
            uint32_t nA = aBase + sn * 8192u;
            uint32_t nB = bBase + sn * 8192u;
            #pragma unroll
            for (int j = 0; j < 2; j++) {
                cp16(nA + dstOff[j],
                     A + (size_t)(bm + srow[j]) * K + cn * 32 + su[j] * 8);
                cp16(nB + dstOff[j],
                     W + (size_t)(bn + srow[j]) * K + cn * 32 + su[j] * 8);
            }
        }
        asm volatile("cp.async.commit_group;" ::: "memory");

        st = (st + 1 == GST) ? 0 : st + 1;
        sn = (sn + 1 == GST) ? 0 : sn + 1;
    }

    int g = lane >> 2;
    int t = lane & 3;
    #pragma unroll
    for (int mt = 0; mt < 2; mt++) {
        #pragma unroll
        for (int half = 0; half < 2; half++) {
            int row = bm + wm + mt * 16 + half * 8 + g;
            const float* xrow = (MODE != 0) ? (X + (size_t)row * N) : nullptr;
            #pragma unroll
            for (int nt = 0; nt < 8; nt++) {
                int col = bn + wn + nt * 8 + 2 * t;
                float2 v;
                v.x = acc[mt][nt][half * 2 + 0];
                v.y = acc[mt][nt][half * 2 + 1];
                if (MODE == 1) {
                    float2 xv = *(const float2*)(xrow + col);
                    v.x += xv.x; v.y += xv.y;
                }
                if (MODE == 2) {
                    float2 xv = *(const float2*)(xrow + col);
                    v.x *= xv.x / (1.f + expf(-xv.x));
                    v.y *= xv.y / (1.f + expf(-xv.y));
                }
                if (MODE == 2) {
                    __half2 hv = __floats2half2_rn(v.x, v.y);
                    *(uint32_t*)((__half*)Cout + (size_t)row * N + col) =
                        *(uint32_t*)&hv;
                } else {
                    *(float2*)((float*)Cout + (size_t)row * N + col) = v;
                }
            }
        }
    }
}

// ---------------- RoPE + split qkv -> q,k fp16 [B,H,T,dh] -------------------
#define Q_SCALE (0.125f * 1.44269504088896f)   // 1/sqrt(64) * log2(e)
__global__ void rope_split_h_kernel(const float* __restrict__ qkv,
                                    __half* __restrict__ q,
                                    __half* __restrict__ k) {
    int idx = blockIdx.x * blockDim.x + threadIdx.x;
    int i = idx & 31;
    int h = (idx >> 5) & 15;
    int m = idx >> 9;
    int b = m >> 11;
    int t = m & 2047;

    const float* base = qkv + (size_t)m * (3 * C_DIM) + h * DH + 2 * i;
    float q1 = base[0],     q2 = base[1];
    float k1 = base[C_DIM], k2 = base[C_DIM + 1];

    float freq = expf(-(2.0f * (float)i) * (1.0f / 64.0f) * 9.210340371976184f);
    float th = (float)t * freq;
    float s, c;
    sincosf(th, &s, &c);

    size_t o = ((size_t)(b * H_NUM + h) * T_LEN + t) * DH + 2 * i;
    __half2 qh = __floats2half2_rn((q1 * c - q2 * s) * Q_SCALE,
                                   (q1 * s + q2 * c) * Q_SCALE);
    __half2 kh = __floats2half2_rn(k1 * c - k2 * s, k1 * s + k2 * c);
    *(uint32_t*)(q + o) = *(uint32_t*)&qh;
    *(uint32_t*)(k + o) = *(uint32_t*)&kh;
}

// ---------------- V transpose: qkv v-section -> [B,H,dh,T] fp16 -------------
__global__ void vtrans_h_kernel(const float* __restrict__ qkv,
                                __half* __restrict__ vt) {
    __shared__ float s[64][65];
    int bh = blockIdx.y;
    int b  = bh >> 4;
    int h  = bh & 15;
    int t0 = blockIdx.x * 64;
    int tid = threadIdx.x;

    for (int idx = tid; idx < 64 * 64; idx += 256) {
        int tok = idx >> 6, d = idx & 63;
        s[tok][d] = qkv[(size_t)(b * T_LEN + t0 + tok) * (3 * C_DIM)
                        + 2 * C_DIM + h * DH + d];
    }
    __syncthreads();
    for (int idx = tid; idx < 64 * 32; idx += 256) {
        int d = idx >> 5, tp = idx & 31;
        __half2 hv = __floats2half2_rn(s[2 * tp][d], s[2 * tp + 1][d]);
        *(uint32_t*)(vt + ((size_t)bh * DH + d) * T_LEN + t0 + 2 * tp) =
            *(uint32_t*)&hv;
    }
}

// ---------------- fp16 causal flash attention (R11 proven: 64-q blocks) -----
#define HPAD 72
#define ONES16 0x3C003C00u
__global__ __launch_bounds__(128)
void attn_h_kernel(const __half* __restrict__ Q,
                   const __half* __restrict__ Kg,
                   const __half* __restrict__ Vt,
                   __half* __restrict__ O) {
    __shared__ __align__(16) __half sQ[64 * HPAD];   // later: P
    __shared__ __align__(16) __half sK[64 * HPAD];
    __shared__ __align__(16) __half sV[64 * HPAD];

    int bh   = blockIdx.y;
    int b    = bh >> 4;
    int head = bh & 15;
    int q0   = blockIdx.x * 64;
    int tid  = threadIdx.x;
    int warp = tid >> 5;
    int lane = tid & 31;
    int wm   = warp * 16;
    int g    = lane >> 2;
    int t    = lane & 3;
    int l15  = lane & 15;
    int lh   = lane >> 4;

    uint32_t qB = (uint32_t)__cvta_generic_to_shared(sQ);
    uint32_t kB = (uint32_t)__cvta_generic_to_shared(sK);
    uint32_t vB = (uint32_t)__cvta_generic_to_shared(sV);

    const __half* qg = Q + ((size_t)bh * T_LEN + q0) * DH;
    #pragma unroll
    for (int idx = tid; idx < 512; idx += 128) {
        int r = idx >> 3, u = idx & 7;
        *(uint4*)&sQ[r * HPAD + u * 8] = *(const uint4*)(qg + r * DH + u * 8);
    }
    __syncthreads();

    uint32_t qf[4][4];
    #pragma unroll
    for (int kc = 0; kc < 4; kc++) {
        int row = wm + l15;
        int u   = kc * 2 + lh;
        ldsm4(qf[kc][0], qf[kc][1], qf[kc][2], qf[kc][3],
              qB + (uint32_t)(row * HPAD + u * 8) * 2u);
    }
    __syncthreads();   // sQ now reusable as P

    float accO[8][4];
    #pragma unroll
    for (int nt = 0; nt < 8; nt++)
        #pragma unroll
        for (int e = 0; e < 4; e++) accO[nt][e] = 0.f;
    float lacc[4] = {0.f, 0.f, 0.f, 0.f};
    float m0 = -1e30f, m1 = -1e30f;

    int r0 = q0 + wm + g;
    int r1 = r0 + 8;
    int prow0 = (wm + g) * HPAD;
    int prow1 = (wm + g + 8) * HPAD;

    int ntiles = q0 / 64 + 1;
    for (int kt = 0; kt < ntiles; kt++) {
        int ks = kt * 64;
        const __half* kbase = Kg + ((size_t)bh * T_LEN + ks) * DH;
        const __half* vbase = Vt + (size_t)bh * DH * T_LEN + ks;
        #pragma unroll
        for (int idx = tid; idx < 512; idx += 128) {
            int r = idx >> 3, u = idx & 7;
            *(uint4*)&sK[r * HPAD + u * 8] = *(const uint4*)(kbase + r * DH + u * 8);
            *(uint4*)&sV[r * HPAD + u * 8] =
                *(const uint4*)(vbase + (size_t)r * T_LEN + u * 8);
        }
        __syncthreads();

        if (ks <= q0 + wm + 15) {
            float s[8][4];
            #pragma unroll
            for (int nt = 0; nt < 8; nt++)
                #pragma unroll
                for (int e = 0; e < 4; e++) s[nt][e] = 0.f;

            #pragma unroll
            for (int kc = 0; kc < 4; kc++) {
                uint32_t bR[2][2][4];
                #pragma unroll
                for (int kh = 0; kh < 2; kh++)
                    #pragma unroll
                    for (int gb = 0; gb < 2; gb++) {
                        int row = gb * 32 + lane;
                        int u   = kc * 2 + kh;
                        ldsm4(bR[kh][gb][0], bR[kh][gb][1],
                              bR[kh][gb][2], bR[kh][gb][3],
                              kB + (uint32_t)(row * HPAD + u * 8) * 2u);
                    }
                #pragma unroll
                for (int nt = 0; nt < 8; nt++)
                    mma_f16(s[nt], qf[kc][0], qf[kc][1], qf[kc][2], qf[kc][3],
                            bR[0][nt >> 2][nt & 3], bR[1][nt >> 2][nt & 3]);
            }

            if (ks + 63 > q0 + wm) {
                #pragma unroll
                for (int nt = 0; nt < 8; nt++) {
                    int kc = ks + nt * 8 + 2 * t;
                    if (kc     > r0) s[nt][0] = -1e30f;
                    if (kc + 1 > r0) s[nt][1] = -1e30f;
                    if (kc     > r1) s[nt][2] = -1e30f;
                    if (kc + 1 > r1) s[nt][3] = -1e30f;
                }
            }

            float tm0 = -1e30f, tm1 = -1e30f;
            #pragma unroll
            for (int nt = 0; nt < 8; nt++) {
                tm0 = fmaxf(tm0, fmaxf(s[nt][0], s[nt][1]));
                tm1 = fmaxf(tm1, fmaxf(s[nt][2], s[nt][3]));
            }
            tm0 = fmaxf(tm0, __shfl_xor_sync(0xffffffffu, tm0, 1));
            tm0 = fmaxf(tm0, __shfl_xor_sync(0xffffffffu, tm0, 2));
            tm1 = fmaxf(tm1, __shfl_xor_sync(0xffffffffu, tm1, 1));
            tm1 = fmaxf(tm1, __shfl_xor_sync(0xffffffffu, tm1, 2));

            float mn0 = fmaxf(m0, tm0), mn1 = fmaxf(m1, tm1);
            float c0 = exp2f(m0 - mn0), c1 = exp2f(m1 - mn1);
            m0 = mn0; m1 = mn1;

            #pragma unroll
            for (int nt = 0; nt < 8; nt++) {
                uint32_t ha, hb;
                asm("cvt.rn.f16x2.f32 %0, %1, %2;" : "=r"(ha)
                    : "f"(s[nt][1] - mn0), "f"(s[nt][0] - mn0));
                asm("cvt.rn.f16x2.f32 %0, %1, %2;" : "=r"(hb)
                    : "f"(s[nt][3] - mn1), "f"(s[nt][2] - mn1));
                asm("ex2.approx.f16x2 %0, %1;" : "=r"(ha) : "r"(ha));
                asm("ex2.approx.f16x2 %0, %1;" : "=r"(hb) : "r"(hb));
                int col = nt * 8 + 2 * t;
                *(uint32_t*)&sQ[prow0 + col] = ha;
                *(uint32_t*)&sQ[prow1 + col] = hb;
            }

            #pragma unroll
            for (int nt = 0; nt < 8; nt++) {
                accO[nt][0] *= c0; accO[nt][1] *= c0;
                accO[nt][2] *= c1; accO[nt][3] *= c1;
            }
            lacc[0] *= c0; lacc[1] *= c0;
            lacc[2] *= c1; lacc[3] *= c1;
            __syncwarp();

            #pragma unroll
            for (int kc = 0; kc < 4; kc++) {
                uint32_t aP[4];
                {
                    int row = wm + l15;
                    int u   = kc * 2 + lh;
                    ldsm4(aP[0], aP[1], aP[2], aP[3],
                          qB + (uint32_t)(row * HPAD + u * 8) * 2u);
                }
                mma_f16(lacc, aP[0], aP[1], aP[2], aP[3], ONES16, ONES16);
                uint32_t bV[2][2][4];
                #pragma unroll
                for (int kh = 0; kh < 2; kh++)
                    #pragma unroll
                    for (int gb = 0; gb < 2; gb++) {
                        int row = gb * 32 + lane;
                        int u   = kc * 2 + kh;
                        ldsm4(bV[kh][gb][0], bV[kh][gb][1],
                              bV[kh][gb][2], bV[kh][gb][3],
                              vB + (uint32_t)(row * HPAD + u * 8) * 2u);
                    }
                #pragma unroll
                for (int nt = 0; nt < 8; nt++)
                    mma_f16(accO[nt], aP[0], aP[1], aP[2], aP[3],
                            bV[0][nt >> 2][nt & 3], bV[1][nt >> 2][nt & 3]);
            }
        }
        __syncthreads();
    }

    float inv0 = 1.f / lacc[0], inv1 = 1.f / lacc[2];
    __half* o0 = O + ((size_t)(b * T_LEN + r0)) * C_DIM + head * DH;
    __half* o1 = O + ((size_t)(b * T_LEN + r1)) * C_DIM + head * DH;
    #pragma unroll
    for (int nt = 0; nt < 8; nt++) {
        int col = nt * 8 + 2 * t;
        __half2 h0 = __floats2half2_rn(accO[nt][0] * inv0, accO[nt][1] * inv0);
        __half2 h1 = __floats2half2_rn(accO[nt][2] * inv1, accO[nt][3] * inv1);
        *(uint32_t*)(o0 + col) = *(uint32_t*)&h0;
        *(uint32_t*)(o1 + col) = *(uint32_t*)&h1;
    }
}

// ---------------- launch ----------------------------------------------------
extern "C" void kernel_launch(void* const* d_in, const int* in_sizes, int n_in,
                              void* d_out, int out_size) {
    const float* x      = (const float*)d_in[0];
    const float* w_qkv  = (const float*)d_in[1];
    const float* w_proj = (const float*)d_in[2];
    const float* g1     = (const float*)d_in[3];
    const float* g2     = (const float*)d_in[4];
    const float* w1     = (const float*)d_in[5];
    const float* w2     = (const float*)d_in[6];
    const float* w3     = (const float*)d_in[7];
    float* out = (float*)d_out;

    __half *p_h16, *p_q16, *p_k16, *p_v16, *p_o16, *p_ff16, *p_w16;
    float  *p_qkv, *p_x1, *p_ff;
    cudaGetSymbolAddress((void**)&p_h16,  g_h16);
    cudaGetSymbolAddress((void**)&p_qkv,  g_qkv);
    cudaGetSymbolAddress((void**)&p_q16,  g_q16);
    cudaGetSymbolAddress((void**)&p_k16,  g_k16);
    cudaGetSymbolAddress((void**)&p_v16,  g_v16);
    cudaGetSymbolAddress((void**)&p_o16,  g_o16);
    cudaGetSymbolAddress((void**)&p_x1,   g_x1);
    cudaGetSymbolAddress((void**)&p_ff,   g_ff);
    cudaGetSymbolAddress((void**)&p_ff16, g_ff16);
    cudaGetSymbolAddress((void**)&p_w16,  g_w16);

    __half* w_qkv16  = p_w16;
    __half* w_proj16 = w_qkv16  + 3 * C_DIM * C_DIM;
    __half* w116     = w_proj16 + C_DIM * C_DIM;
    __half* w216     = w116     + 4 * C_DIM * C_DIM;
    __half* w316     = w216     + 4 * C_DIM * C_DIM;

    // single fused weight conversion
    f2h_all_kernel<<<2048, 256>>>(w_qkv, w_proj, w1, w2, w3, p_w16);

    rmsnorm_h_kernel<<<M_TOK, 256>>>(x, g1, p_h16);
    hgemm_kernel<0><<<dim3(3 * C_DIM / 128, M_TOK / 128), 256>>>(
        p_h16, w_qkv16, nullptr, p_qkv, M_TOK, 3 * C_DIM, C_DIM);
    rope_split_h_kernel<<<(M_TOK * H_NUM * 32) / 256, 256>>>(p_qkv, p_q16, p_k16);
    vtrans_h_kernel<<<dim3(T_LEN / 64, B_NUM * H_NUM), 256>>>(p_qkv, p_v16);
    attn_h_kernel<<<dim3(T_LEN / 64, B_NUM * H_NUM), 128>>>(
        p_q16, p_k16, p_v16, p_o16);
    hgemm_kernel<1><<<dim3(C_DIM / 128, M_TOK / 128), 256>>>(
        p_o16, w_proj16, x, p_x1, M_TOK, C_DIM, C_DIM);
    rmsnorm_h_kernel<<<M_TOK, 256>>>(p_x1, g2, p_h16);
    hgemm_kernel<0><<<dim3(FF_DIM / 128, M_TOK / 128), 256>>>(
        p_h16, w116, nullptr, p_ff, M_TOK, FF_DIM, C_DIM);
    hgemm_kernel<2><<<dim3(FF_DIM / 128, M_TOK / 128), 256>>>(
        p_h16, w316, p_ff, p_ff16, M_TOK, FF_DIM, C_DIM);
    hgemm_kernel<1><<<dim3(C_DIM / 128, M_TOK / 128), 256>>>(
        p_ff16, w216, p_x1, out, M_TOK, C_DIM, FF_DIM);
}

// round 14
// speedup vs baseline: 1.0560x; 1.0269x over previous
#include <cuda_runtime.h>
#include <cuda_fp16.h>
#include <math.h>
#include <stdint.h>

#define C_DIM   1024
#define H_NUM   16
#define DH      64
#define FF_DIM  4096
#define B_NUM   2
#define T_LEN   2048
#define M_TOK   4096   // B*T

// ---------------- scratch (device globals; no allocation allowed) ----------
__device__ __half g_h16 [M_TOK * C_DIM];       // rmsnorm out (fp16)
__device__ float  g_qkv [M_TOK * 3 * C_DIM];
__device__ __half g_q16 [M_TOK * C_DIM];       // [B,H,T,dh] (pre-scaled fp16)
__device__ __half g_k16 [M_TOK * C_DIM];       // [B,H,T,dh] fp16
__device__ __half g_v16 [M_TOK * C_DIM];       // [B,H,dh,T] fp16 (transposed)
__device__ __half g_o16 [M_TOK * C_DIM];       // attention out (fp16)
__device__ float  g_x1  [M_TOK * C_DIM];
__device__ float  g_ff  [M_TOK * FF_DIM];      // a = h2 @ w1^T (fp32)
__device__ __half g_ff16[M_TOK * FF_DIM];      // silu(a)*b (fp16)
__device__ __half g_w16 [16 * C_DIM * C_DIM];  // all weights fp16 (16M halves)

// ---------------- helpers ----------------------------------------------------
__device__ __forceinline__ void mma_f16(float c[4],
                                        uint32_t a0, uint32_t a1, uint32_t a2, uint32_t a3,
                                        uint32_t b0, uint32_t b1) {
    asm volatile(
        "mma.sync.aligned.m16n8k16.row.col.f32.f16.f16.f32 "
        "{%0,%1,%2,%3}, {%4,%5,%6,%7}, {%8,%9}, {%0,%1,%2,%3};\n"
        : "+f"(c[0]), "+f"(c[1]), "+f"(c[2]), "+f"(c[3])
        : "r"(a0), "r"(a1), "r"(a2), "r"(a3), "r"(b0), "r"(b1));
}
__device__ __forceinline__ void ldsm4(uint32_t& r0, uint32_t& r1,
                                      uint32_t& r2, uint32_t& r3, uint32_t addr) {
    asm volatile("ldmatrix.sync.aligned.m8n8.x4.shared.b16 {%0,%1,%2,%3}, [%4];"
                 : "=r"(r0), "=r"(r1), "=r"(r2), "=r"(r3) : "r"(addr));
}
__device__ __forceinline__ void cp16(uint32_t dst, const void* src) {
    asm volatile("cp.async.cg.shared.global [%0], [%1], 16;" :: "r"(dst), "l"(src));
}

// ---------------- fused fp32 -> fp16 weight convert (single launch) ---------
__global__ void f2h_all_kernel(const float* __restrict__ w_qkv,
                               const float* __restrict__ w_proj,
                               const float* __restrict__ w1,
                               const float* __restrict__ w2,
                               const float* __restrict__ w3,
                               __half* __restrict__ out) {
    int unit = blockIdx.x >> 7;
    const float* src;
    if (unit < 3)       src = w_qkv  + ((size_t)unit << 20);
    else if (unit < 4)  src = w_proj;
    else if (unit < 8)  src = w1 + ((size_t)(unit - 4) << 20);
    else if (unit < 12) src = w2 + ((size_t)(unit - 8) << 20);
    else                src = w3 + ((size_t)(unit - 12) << 20);
    __half* dst = out + ((size_t)unit << 20);

    size_t local = (size_t)(blockIdx.x & 127) * 8192 + threadIdx.x * 8;
    #pragma unroll
    for (int j = 0; j < 4; j++) {
        size_t idx = local + (size_t)j * 2048;
        float4 a = *(const float4*)(src + idx);
        float4 b = *(const float4*)(src + idx + 4);
        __half2 h0 = __floats2half2_rn(a.x, a.y);
        __half2 h1 = __floats2half2_rn(a.z, a.w);
        __half2 h2 = __floats2half2_rn(b.x, b.y);
        __half2 h3 = __floats2half2_rn(b.z, b.w);
        uint4 u;
        u.x = *(uint32_t*)&h0; u.y = *(uint32_t*)&h1;
        u.z = *(uint32_t*)&h2; u.w = *(uint32_t*)&h3;
        *(uint4*)(dst + idx) = u;
    }
}

// ---------------- RMSNorm -> fp16 --------------------------------------------
__global__ void rmsnorm_h_kernel(const float* __restrict__ x,
                                 const float* __restrict__ g,
                                 __half* __restrict__ y) {
    int row = blockIdx.x;
    int tid = threadIdx.x;
    const float4* xr = (const float4*)(x + (size_t)row * C_DIM);
    const float4* gr = (const float4*)g;

    float4 xv = xr[tid];
    float ss = xv.x*xv.x + xv.y*xv.y + xv.z*xv.z + xv.w*xv.w;
    #pragma unroll
    for (int off = 16; off > 0; off >>= 1)
        ss += __shfl_xor_sync(0xffffffffu, ss, off);
    __shared__ float red[8];
    if ((tid & 31) == 0) red[tid >> 5] = ss;
    __syncthreads();
    float tot = 0.f;
    #pragma unroll
    for (int i = 0; i < 8; i++) tot += red[i];
    float inv = rsqrtf(tot * (1.0f / C_DIM) + 1e-5f);

    float4 gv = gr[tid];
    __half2 h0 = __floats2half2_rn(xv.x * gv.x * inv, xv.y * gv.y * inv);
    __half2 h1 = __floats2half2_rn(xv.z * gv.z * inv, xv.w * gv.w * inv);
    uint2 u;
    u.x = *(uint32_t*)&h0; u.y = *(uint32_t*)&h1;
    *(uint2*)(y + (size_t)row * C_DIM + tid * 4) = u;
}

// ---------------- fp16 tensor-core GEMM (R11 proven: k32, 3-stage) ----------
#define GST 3
template <int MODE>
__global__ __launch_bounds__(256, 2)
void hgemm_kernel(const __half* __restrict__ A, const __half* __restrict__ W,
                  const float* X, void* Cout, int M, int N, int K) {
    __shared__ __align__(16) __half sA[GST][128 * 32];
    __shared__ __align__(16) __half sB[GST][128 * 32];

    int tid  = threadIdx.x;
    int bm   = blockIdx.y * 128;
    int bn   = blockIdx.x * 128;
    int warp = tid >> 5;
    int lane = tid & 31;
    int wm   = (warp >> 1) * 32;
    int wn   = (warp & 1) * 64;

    uint32_t dstOff[2];
    int srow[2], su[2];
    #pragma unroll
    for (int j = 0; j < 2; j++) {
        int idx = tid + 256 * j;
        int row = idx >> 2, u = idx & 3;
        int uz  = u ^ ((row >> 1) & 3);
        dstOff[j] = (uint32_t)(row * 32 + uz * 8) * 2u;
        srow[j] = row; su[j] = u;
    }

    uint32_t aBase = (uint32_t)__cvta_generic_to_shared(&sA[0][0]);
    uint32_t bBase = (uint32_t)__cvta_generic_to_shared(&sB[0][0]);

    int l15 = lane & 15, lh = lane >> 4;
    uint32_t offA[2][2];
    #pragma unroll
    for (int q = 0; q < 2; q++)
        #pragma unroll
        for (int mt = 0; mt < 2; mt++) {
            int row = wm + mt * 16 + l15;
            int u   = 2 * q + lh;
            int uz  = u ^ ((row >> 1) & 3);
            offA[q][mt] = (uint32_t)(row * 32 + uz * 8) * 2u;
        }
    uint32_t offB[2][2][2];
    #pragma unroll
    for (int q = 0; q < 2; q++)
        #pragma unroll
        for (int kh = 0; kh < 2; kh++)
            #pragma unroll
            for (int gb = 0; gb < 2; gb++) {
                int row = wn + gb * 32 + lane;
                int u   = 2 * q + kh;
                int uz  = u ^ ((row >> 1) & 3);
                offB[q][kh][gb] = (uint32_t)(row * 32 + uz * 8) * 2u;
            }

    float acc[2][8][4];
    #pragma unroll
    for (int mt = 0; mt < 2; mt++)
        #pragma unroll
        for (int nt = 0; nt < 8; nt++)
            #pragma unroll
            for (int e = 0; e < 4; e++) acc[mt][nt][e] = 0.f;

    int NC = K >> 5;

    #pragma unroll
    for (int s = 0; s < 2; s++) {
        #pragma unroll
        for (int j = 0; j < 2; j++) {
            cp16(aBase + s * 8192u + dstOff[j],
                 A + (size_t)(bm + srow[j]) * K + s * 32 + su[j] * 8);
            cp16(bBase + s * 8192u + dstOff[j],
                 W + (size_t)(bn + srow[j]) * K + s * 32 + su[j] * 8);
        }
        asm volatile("cp.async.commit_group;" ::: "memory");
    }

    int st = 0, sn = 2;
    for (int ck = 0; ck < NC; ck++) {
        asm volatile("cp.async.wait_group 1;" ::: "memory");
        __syncthreads();

        uint32_t tA = aBase + st * 8192u;
        uint32_t tB = bBase + st * 8192u;
        #pragma unroll
        for (int q = 0; q < 2; q++) {
            uint32_t aR[2][4], bR[2][2][4];
            ldsm4(aR[0][0], aR[0][1], aR[0][2], aR[0][3], tA + offA[q][0]);
            ldsm4(aR[1][0], aR[1][1], aR[1][2], aR[1][3], tA + offA[q][1]);
            #pragma unroll
            for (int kh = 0; kh < 2; kh++)
                #pragma unroll
                for (int gb = 0; gb < 2; gb++)
                    ldsm4(bR[kh][gb][0], bR[kh][gb][1], bR[kh][gb][2], bR[kh][gb][3],
                          tB + offB[q][kh][gb]);
            #pragma unroll
            for (int mt = 0; mt < 2; mt++)
                #pragma unroll
                for (int nt = 0; nt < 8; nt++)
                    mma_f16(acc[mt][nt],
                            aR[mt][0], aR[mt][1], aR[mt][2], aR[mt][3],
                            bR[0][nt >> 2][nt & 3], bR[1][nt >> 2][nt & 3]);
        }

        int cn = ck + 2;
        if (cn < NC) {
            uint32_t nA = aBase + sn * 8192u;
            uint32_t nB = bBase + sn * 8192u;
            #pragma unroll
            for (int j = 0; j < 2; j++) {
                cp16(nA + dstOff[j],
                     A + (size_t)(bm + srow[j]) * K + cn * 32 + su[j] * 8);
                cp16(nB + dstOff[j],
                     W + (size_t)(bn + srow[j]) * K + cn * 32 + su[j] * 8);
            }
        }
        asm volatile("cp.async.commit_group;" ::: "memory");

        st = (st + 1 == GST) ? 0 : st + 1;
        sn = (sn + 1 == GST) ? 0 : sn + 1;
    }

    int g = lane >> 2;
    int t = lane & 3;
    #pragma unroll
    for (int mt = 0; mt < 2; mt++) {
        #pragma unroll
        for (int half = 0; half < 2; half++) {
            int row = bm + wm + mt * 16 + half * 8 + g;
            const float* xrow = (MODE != 0) ? (X + (size_t)row * N) : nullptr;
            #pragma unroll
            for (int nt = 0; nt < 8; nt++) {
                int col = bn + wn + nt * 8 + 2 * t;
                float2 v;
                v.x = acc[mt][nt][half * 2 + 0];
                v.y = acc[mt][nt][half * 2 + 1];
                if (MODE == 1) {
                    float2 xv = *(const float2*)(xrow + col);
                    v.x += xv.x; v.y += xv.y;
                }
                if (MODE == 2) {
                    float2 xv = *(const float2*)(xrow + col);
                    v.x *= xv.x / (1.f + expf(-xv.x));
                    v.y *= xv.y / (1.f + expf(-xv.y));
                }
                if (MODE == 2) {
                    __half2 hv = __floats2half2_rn(v.x, v.y);
                    *(uint32_t*)((__half*)Cout + (size_t)row * N + col) =
                        *(uint32_t*)&hv;
                } else {
                    *(float2*)((float*)Cout + (size_t)row * N + col) = v;
                }
            }
        }
    }
}

// ---------------- RoPE + split qkv -> q,k fp16 [B,H,T,dh] -------------------
#define Q_SCALE (0.125f * 1.44269504088896f)   // 1/sqrt(64) * log2(e)
__global__ void rope_split_h_kernel(const float* __restrict__ qkv,
                                    __half* __restrict__ q,
                                    __half* __restrict__ k) {
    int idx = blockIdx.x * blockDim.x + threadIdx.x;
    int i = idx & 31;
    int h = (idx >> 5) & 15;
    int m = idx >> 9;
    int b = m >> 11;
    int t = m & 2047;

    const float* base = qkv + (size_t)m * (3 * C_DIM) + h * DH + 2 * i;
    float q1 = base[0],     q2 = base[1];
    float k1 = base[C_DIM], k2 = base[C_DIM + 1];

    float freq = expf(-(2.0f * (float)i) * (1.0f / 64.0f) * 9.210340371976184f);
    float th = (float)t * freq;
    float s, c;
    sincosf(th, &s, &c);

    size_t o = ((size_t)(b * H_NUM + h) * T_LEN + t) * DH + 2 * i;
    __half2 qh = __floats2half2_rn((q1 * c - q2 * s) * Q_SCALE,
                                   (q1 * s + q2 * c) * Q_SCALE);
    __half2 kh = __floats2half2_rn(k1 * c - k2 * s, k1 * s + k2 * c);
    *(uint32_t*)(q + o) = *(uint32_t*)&qh;
    *(uint32_t*)(k + o) = *(uint32_t*)&kh;
}

// ---------------- V transpose: qkv v-section -> [B,H,dh,T] fp16 -------------
__global__ void vtrans_h_kernel(const float* __restrict__ qkv,
                                __half* __restrict__ vt) {
    __shared__ float s[64][65];
    int bh = blockIdx.y;
    int b  = bh >> 4;
    int h  = bh & 15;
    int t0 = blockIdx.x * 64;
    int tid = threadIdx.x;

    for (int idx = tid; idx < 64 * 64; idx += 256) {
        int tok = idx >> 6, d = idx & 63;
        s[tok][d] = qkv[(size_t)(b * T_LEN + t0 + tok) * (3 * C_DIM)
                        + 2 * C_DIM + h * DH + d];
    }
    __syncthreads();
    for (int idx = tid; idx < 64 * 32; idx += 256) {
        int d = idx >> 5, tp = idx & 31;
        __half2 hv = __floats2half2_rn(s[2 * tp][d], s[2 * tp + 1][d]);
        *(uint32_t*)(vt + ((size_t)bh * DH + d) * T_LEN + t0 + 2 * tp) =
            *(uint32_t*)&hv;
    }
}

// ---------------- fp16 causal flash attention, cp.async double-buffered K/V -
#define HPAD 72
#define ONES16 0x3C003C00u
#define KV_TILE (64 * HPAD)
__global__ __launch_bounds__(128)
void attn_h_kernel(const __half* __restrict__ Q,
                   const __half* __restrict__ Kg,
                   const __half* __restrict__ Vt,
                   __half* __restrict__ O) {
    __shared__ __align__(16) __half sQ[64 * HPAD];     // later: P
    __shared__ __align__(16) __half sK[2][KV_TILE];
    __shared__ __align__(16) __half sV[2][KV_TILE];

    int bh   = blockIdx.y;
    int b    = bh >> 4;
    int head = bh & 15;
    int q0   = blockIdx.x * 64;
    int tid  = threadIdx.x;
    int warp = tid >> 5;
    int lane = tid & 31;
    int wm   = warp * 16;
    int g    = lane >> 2;
    int t    = lane & 3;
    int l15  = lane & 15;
    int lh   = lane >> 4;

    uint32_t qB = (uint32_t)__cvta_generic_to_shared(sQ);
    uint32_t kB = (uint32_t)__cvta_generic_to_shared(&sK[0][0]);
    uint32_t vB = (uint32_t)__cvta_generic_to_shared(&sV[0][0]);

    const __half* kg0 = Kg + (size_t)bh * T_LEN * DH;
    const __half* vg0 = Vt + (size_t)bh * DH * T_LEN;

    // per-thread K/V cp.async mapping: 4 16B units each (64 rows x 8 units)
    int cr[4], cu[4];
    uint32_t cOff[4];
    #pragma unroll
    for (int j = 0; j < 4; j++) {
        int idx = tid + 128 * j;
        cr[j] = idx >> 3; cu[j] = idx & 7;
        cOff[j] = (uint32_t)(cr[j] * HPAD + cu[j] * 8) * 2u;
    }

    // load Q tile (synchronous; once)
    const __half* qg = Q + ((size_t)bh * T_LEN + q0) * DH;
    #pragma unroll
    for (int idx = tid; idx < 512; idx += 128) {
        int r = idx >> 3, u = idx & 7;
        *(uint4*)&sQ[r * HPAD + u * 8] = *(const uint4*)(qg + r * DH + u * 8);
    }

    // prefetch K/V tile 0 into stage 0
    #pragma unroll
    for (int j = 0; j < 4; j++) {
        cp16(kB + cOff[j], kg0 + (size_t)cr[j] * DH + cu[j] * 8);
        cp16(vB + cOff[j], vg0 + (size_t)cr[j] * T_LEN + cu[j] * 8);
    }
    asm volatile("cp.async.commit_group;" ::: "memory");
    __syncthreads();

    // Q fragments
    uint32_t qf[4][4];
    #pragma unroll
    for (int kc = 0; kc < 4; kc++) {
        int row = wm + l15;
        int u   = kc * 2 + lh;
        ldsm4(qf[kc][0], qf[kc][1], qf[kc][2], qf[kc][3],
              qB + (uint32_t)(row * HPAD + u * 8) * 2u);
    }
    __syncthreads();   // sQ now reusable as P

    float accO[8][4];
    #pragma unroll
    for (int nt = 0; nt < 8; nt++)
        #pragma unroll
        for (int e = 0; e < 4; e++) accO[nt][e] = 0.f;
    float lacc[4] = {0.f, 0.f, 0.f, 0.f};
    float m0 = -1e30f, m1 = -1e30f;

    int r0 = q0 + wm + g;
    int r1 = r0 + 8;
    int prow0 = (wm + g) * HPAD;
    int prow1 = (wm + g + 8) * HPAD;

    int ntiles = q0 / 64 + 1;
    for (int kt = 0; kt < ntiles; kt++) {
        int st = kt & 1;

        // prefetch next tile into other stage
        bool more = (kt + 1) < ntiles;
        if (more) {
            int ks1 = (kt + 1) * 64;
            uint32_t kS = kB + (st ^ 1) * (KV_TILE * 2);
            uint32_t vS = vB + (st ^ 1) * (KV_TILE * 2);
            const __half* kbase = kg0 + (size_t)ks1 * DH;
            const __half* vbase = vg0 + ks1;
            #pragma unroll
            for (int j = 0; j < 4; j++) {
                cp16(kS + cOff[j], kbase + (size_t)cr[j] * DH + cu[j] * 8);
                cp16(vS + cOff[j], vbase + (size_t)cr[j] * T_LEN + cu[j] * 8);
            }
        }
        asm volatile("cp.async.commit_group;" ::: "memory");
        // wait for current tile (1 newer group = the prefetch just issued)
        if (more)
            asm volatile("cp.async.wait_group 1;" ::: "memory");
        else
            asm volatile("cp.async.wait_group 0;" ::: "memory");
        __syncthreads();

        int ks = kt * 64;
        uint32_t kT = kB + st * (KV_TILE * 2);
        uint32_t vT = vB + st * (KV_TILE * 2);

        if (ks <= q0 + wm + 15) {
            // ---- S = Q @ K^T ----
            float s[8][4];
            #pragma unroll
            for (int nt = 0; nt < 8; nt++)
                #pragma unroll
                for (int e = 0; e < 4; e++) s[nt][e] = 0.f;

            #pragma unroll
            for (int kc = 0; kc < 4; kc++) {
                uint32_t bR[2][2][4];
                #pragma unroll
                for (int kh = 0; kh < 2; kh++)
                    #pragma unroll
                    for (int gb = 0; gb < 2; gb++) {
                        int row = gb * 32 + lane;
                        int u   = kc * 2 + kh;
                        ldsm4(bR[kh][gb][0], bR[kh][gb][1],
                              bR[kh][gb][2], bR[kh][gb][3],
                              kT + (uint32_t)(row * HPAD + u * 8) * 2u);
                    }
                #pragma unroll
                for (int nt = 0; nt < 8; nt++)
                    mma_f16(s[nt], qf[kc][0], qf[kc][1], qf[kc][2], qf[kc][3],
                            bR[0][nt >> 2][nt & 3], bR[1][nt >> 2][nt & 3]);
            }

            // ---- causal mask ----
            if (ks + 63 > q0 + wm) {
                #pragma unroll
                for (int nt = 0; nt < 8; nt++) {
                    int kc = ks + nt * 8 + 2 * t;
                    if (kc     > r0) s[nt][0] = -1e30f;
                    if (kc + 1 > r0) s[nt][1] = -1e30f;
                    if (kc     > r1) s[nt][2] = -1e30f;
                    if (kc + 1 > r1) s[nt][3] = -1e30f;
                }
            }

            // ---- online softmax ----
            float tm0 = -1e30f, tm1 = -1e30f;
            #pragma unroll
            for (int nt = 0; nt < 8; nt++) {
                tm0 = fmaxf(tm0, fmaxf(s[nt][0], s[nt][1]));
                tm1 = fmaxf(tm1, fmaxf(s[nt][2], s[nt][3]));
            }
            tm0 = fmaxf(tm0, __shfl_xor_sync(0xffffffffu, tm0, 1));
            tm0 = fmaxf(tm0, __shfl_xor_sync(0xffffffffu, tm0, 2));
            tm1 = fmaxf(tm1, __shfl_xor_sync(0xffffffffu, tm1, 1));
            tm1 = fmaxf(tm1, __shfl_xor_sync(0xffffffffu, tm1, 2));

            float mn0 = fmaxf(m0, tm0), mn1 = fmaxf(m1, tm1);
            float c0 = exp2f(m0 - mn0), c1 = exp2f(m1 - mn1);
            m0 = mn0; m1 = mn1;

            #pragma unroll
            for (int nt = 0; nt < 8; nt++) {
                uint32_t ha, hb;
                asm("cvt.rn.f16x2.f32 %0, %1, %2;" : "=r"(ha)
                    : "f"(s[nt][1] - mn0), "f"(s[nt][0] - mn0));
                asm("cvt.rn.f16x2.f32 %0, %1, %2;" : "=r"(hb)
                    : "f"(s[nt][3] - mn1), "f"(s[nt][2] - mn1));
                asm("ex2.approx.f16x2 %0, %1;" : "=r"(ha) : "r"(ha));
                asm("ex2.approx.f16x2 %0, %1;" : "=r"(hb) : "r"(hb));
                int col = nt * 8 + 2 * t;
                *(uint32_t*)&sQ[prow0 + col] = ha;
                *(uint32_t*)&sQ[prow1 + col] = hb;
            }

            #pragma unroll
            for (int nt = 0; nt < 8; nt++) {
                accO[nt][0] *= c0; accO[nt][1] *= c0;
                accO[nt][2] *= c1; accO[nt][3] *= c1;
            }
            lacc[0] *= c0; lacc[1] *= c0;
            lacc[2] *= c1; lacc[3] *= c1;
            __syncwarp();

            // ---- O += P @ V ; l += P @ 1 ----
            #pragma unroll
            for (int kc = 0; kc < 4; kc++) {
                uint32_t aP[4];
                {
                    int row = wm + l15;
                    int u   = kc * 2 + lh;
                    ldsm4(aP[0], aP[1], aP[2], aP[3],
                          qB + (uint32_t)(row * HPAD + u * 8) * 2u);
                }
                mma_f16(lacc, aP[0], aP[1], aP[2], aP[3], ONES16, ONES16);
                uint32_t bV[2][2][4];
                #pragma unroll
                for (int kh = 0; kh < 2; kh++)
                    #pragma unroll
                    for (int gb = 0; gb < 2; gb++) {
                        int row = gb * 32 + lane;
                        int u   = kc * 2 + kh;
                        ldsm4(bV[kh][gb][0], bV[kh][gb][1],
                              bV[kh][gb][2], bV[kh][gb][3],
                              vT + (uint32_t)(row * HPAD + u * 8) * 2u);
                    }
                #pragma unroll
                for (int nt = 0; nt < 8; nt++)
                    mma_f16(accO[nt], aP[0], aP[1], aP[2], aP[3],
                            bV[0][nt >> 2][nt & 3], bV[1][nt >> 2][nt & 3]);
            }
        }
        __syncthreads();   // protect stage overwrite by prefetch 2 tiles ahead
    }

    float inv0 = 1.f / lacc[0], inv1 = 1.f / lacc[2];
    __half* o0 = O + ((size_t)(b * T_LEN + r0)) * C_DIM + head * DH;
    __half* o1 = O + ((size_t)(b * T_LEN + r1)) * C_DIM + head * DH;
    #pragma unroll
    for (int nt = 0; nt < 8; nt++) {
        int col = nt * 8 + 2 * t;
        __half2 h0 = __floats2half2_rn(accO[nt][0] * inv0, accO[nt][1] * inv0);
        __half2 h1 = __floats2half2_rn(accO[nt][2] * inv1, accO[nt][3] * inv1);
        *(uint32_t*)(o0 + col) = *(uint32_t*)&h0;
        *(uint32_t*)(o1 + col) = *(uint32_t*)&h1;
    }
}

// ---------------- launch ----------------------------------------------------
extern "C" void kernel_launch(void* const* d_in, const int* in_sizes, int n_in,
                              void* d_out, int out_size) {
    const float* x      = (const float*)d_in[0];
    const float* w_qkv  = (const float*)d_in[1];
    const float* w_proj = (const float*)d_in[2];
    const float* g1     = (const float*)d_in[3];
    const float* g2     = (const float*)d_in[4];
    const float* w1     = (const float*)d_in[5];
    const float* w2     = (const float*)d_in[6];
    const float* w3     = (const float*)d_in[7];
    float* out = (float*)d_out;

    __half *p_h16, *p_q16, *p_k16, *p_v16, *p_o16, *p_ff16, *p_w16;
    float  *p_qkv, *p_x1, *p_ff;
    cudaGetSymbolAddress((void**)&p_h16,  g_h16);
    cudaGetSymbolAddress((void**)&p_qkv,  g_qkv);
    cudaGetSymbolAddress((void**)&p_q16,  g_q16);
    cudaGetSymbolAddress((void**)&p_k16,  g_k16);
    cudaGetSymbolAddress((void**)&p_v16,  g_v16);
    cudaGetSymbolAddress((void**)&p_o16,  g_o16);
    cudaGetSymbolAddress((void**)&p_x1,   g_x1);
    cudaGetSymbolAddress((void**)&p_ff,   g_ff);
    cudaGetSymbolAddress((void**)&p_ff16, g_ff16);
    cudaGetSymbolAddress((void**)&p_w16,  g_w16);

    __half* w_qkv16  = p_w16;
    __half* w_proj16 = w_qkv16  + 3 * C_DIM * C_DIM;
    __half* w116     = w_proj16 + C_DIM * C_DIM;
    __half* w216     = w116     + 4 * C_DIM * C_DIM;
    __half* w316     = w216     + 4 * C_DIM * C_DIM;

    f2h_all_kernel<<<2048, 256>>>(w_qkv, w_proj, w1, w2, w3, p_w16);

    rmsnorm_h_kernel<<<M_TOK, 256>>>(x, g1, p_h16);
    hgemm_kernel<0><<<dim3(3 * C_DIM / 128, M_TOK / 128), 256>>>(
        p_h16, w_qkv16, nullptr, p_qkv, M_TOK, 3 * C_DIM, C_DIM);
    rope_split_h_kernel<<<(M_TOK * H_NUM * 32) / 256, 256>>>(p_qkv, p_q16, p_k16);
    vtrans_h_kernel<<<dim3(T_LEN / 64, B_NUM * H_NUM), 256>>>(p_qkv, p_v16);
    attn_h_kernel<<<dim3(T_LEN / 64, B_NUM * H_NUM), 128>>>(
        p_q16, p_k16, p_v16, p_o16);
    hgemm_kernel<1><<<dim3(C_DIM / 128, M_TOK / 128), 256>>>(
        p_o16, w_proj16, x, p_x1, M_TOK, C_DIM, C_DIM);
    rmsnorm_h_kernel<<<M_TOK, 256>>>(p_x1, g2, p_h16);
    hgemm_kernel<0><<<dim3(FF_DIM / 128, M_TOK / 128), 256>>>(
        p_h16, w116, nullptr, p_ff, M_TOK, FF_DIM, C_DIM);
    hgemm_kernel<2><<<dim3(FF_DIM / 128, M_TOK / 128), 256>>>(
        p_h16, w316, p_ff, p_ff16, M_TOK, FF_DIM, C_DIM);
    hgemm_kernel<1><<<dim3(C_DIM / 128, M_TOK / 128), 256>>>(
        p_ff16, w216, p_x1, out, M_TOK, C_DIM, FF_DIM);
}

// round 15
// speedup vs baseline: 1.0966x; 1.0384x over previous
#include <cuda_runtime.h>
#include <cuda_fp16.h>
#include <math.h>
#include <stdint.h>

#define C_DIM   1024
#define H_NUM   16
#define DH      64
#define FF_DIM  4096
#define B_NUM   2
#define T_LEN   2048
#define M_TOK   4096   // B*T

// ---------------- scratch (device globals; no allocation allowed) ----------
__device__ __half g_h16 [M_TOK * C_DIM];       // rmsnorm out (fp16)
__device__ __half g_qkv16[M_TOK * 3 * C_DIM];  // qkv (fp16)
__device__ __half g_q16 [M_TOK * C_DIM];       // [B,H,T,dh] (pre-scaled fp16)
__device__ __half g_k16 [M_TOK * C_DIM];       // [B,H,T,dh] fp16
__device__ __half g_v16 [M_TOK * C_DIM];       // [B,H,dh,T] fp16 (transposed)
__device__ __half g_o16 [M_TOK * C_DIM];       // attention out (fp16)
__device__ float  g_x1  [M_TOK * C_DIM];
__device__ __half g_ffa [M_TOK * FF_DIM];      // a = h2 @ w1^T (fp16)
__device__ __half g_ff16[M_TOK * FF_DIM];      // silu(a)*b (fp16)
__device__ __half g_w16 [16 * C_DIM * C_DIM];  // all weights fp16 (16M halves)

// ---------------- helpers ----------------------------------------------------
__device__ __forceinline__ void mma_f16(float c[4],
                                        uint32_t a0, uint32_t a1, uint32_t a2, uint32_t a3,
                                        uint32_t b0, uint32_t b1) {
    asm volatile(
        "mma.sync.aligned.m16n8k16.row.col.f32.f16.f16.f32 "
        "{%0,%1,%2,%3}, {%4,%5,%6,%7}, {%8,%9}, {%0,%1,%2,%3};\n"
        : "+f"(c[0]), "+f"(c[1]), "+f"(c[2]), "+f"(c[3])
        : "r"(a0), "r"(a1), "r"(a2), "r"(a3), "r"(b0), "r"(b1));
}
__device__ __forceinline__ void ldsm4(uint32_t& r0, uint32_t& r1,
                                      uint32_t& r2, uint32_t& r3, uint32_t addr) {
    asm volatile("ldmatrix.sync.aligned.m8n8.x4.shared.b16 {%0,%1,%2,%3}, [%4];"
                 : "=r"(r0), "=r"(r1), "=r"(r2), "=r"(r3) : "r"(addr));
}
__device__ __forceinline__ void cp16(uint32_t dst, const void* src) {
    asm volatile("cp.async.cg.shared.global [%0], [%1], 16;" :: "r"(dst), "l"(src));
}

// ---------------- fused fp32 -> fp16 weight convert (single launch) ---------
__global__ void f2h_all_kernel(const float* __restrict__ w_qkv,
                               const float* __restrict__ w_proj,
                               const float* __restrict__ w1,
                               const float* __restrict__ w2,
                               const float* __restrict__ w3,
                               __half* __restrict__ out) {
    int unit = blockIdx.x >> 7;
    const float* src;
    if (unit < 3)       src = w_qkv  + ((size_t)unit << 20);
    else if (unit < 4)  src = w_proj;
    else if (unit < 8)  src = w1 + ((size_t)(unit - 4) << 20);
    else if (unit < 12) src = w2 + ((size_t)(unit - 8) << 20);
    else                src = w3 + ((size_t)(unit - 12) << 20);
    __half* dst = out + ((size_t)unit << 20);

    size_t local = (size_t)(blockIdx.x & 127) * 8192 + threadIdx.x * 8;
    #pragma unroll
    for (int j = 0; j < 4; j++) {
        size_t idx = local + (size_t)j * 2048;
        float4 a = *(const float4*)(src + idx);
        float4 b = *(const float4*)(src + idx + 4);
        __half2 h0 = __floats2half2_rn(a.x, a.y);
        __half2 h1 = __floats2half2_rn(a.z, a.w);
        __half2 h2 = __floats2half2_rn(b.x, b.y);
        __half2 h3 = __floats2half2_rn(b.z, b.w);
        uint4 u;
        u.x = *(uint32_t*)&h0; u.y = *(uint32_t*)&h1;
        u.z = *(uint32_t*)&h2; u.w = *(uint32_t*)&h3;
        *(uint4*)(dst + idx) = u;
    }
}

// ---------------- RMSNorm -> fp16 --------------------------------------------
__global__ void rmsnorm_h_kernel(const float* __restrict__ x,
                                 const float* __restrict__ g,
                                 __half* __restrict__ y) {
    int row = blockIdx.x;
    int tid = threadIdx.x;
    const float4* xr = (const float4*)(x + (size_t)row * C_DIM);
    const float4* gr = (const float4*)g;

    float4 xv = xr[tid];
    float ss = xv.x*xv.x + xv.y*xv.y + xv.z*xv.z + xv.w*xv.w;
    #pragma unroll
    for (int off = 16; off > 0; off >>= 1)
        ss += __shfl_xor_sync(0xffffffffu, ss, off);
    __shared__ float red[8];
    if ((tid & 31) == 0) red[tid >> 5] = ss;
    __syncthreads();
    float tot = 0.f;
    #pragma unroll
    for (int i = 0; i < 8; i++) tot += red[i];
    float inv = rsqrtf(tot * (1.0f / C_DIM) + 1e-5f);

    float4 gv = gr[tid];
    __half2 h0 = __floats2half2_rn(xv.x * gv.x * inv, xv.y * gv.y * inv);
    __half2 h1 = __floats2half2_rn(xv.z * gv.z * inv, xv.w * gv.w * inv);
    uint2 u;
    u.x = *(uint32_t*)&h0; u.y = *(uint32_t*)&h1;
    *(uint2*)(y + (size_t)row * C_DIM + tid * 4) = u;
}

// ---------------- fp16 tensor-core GEMM (k32, 3-stage cp.async) -------------
// MODE 0: fp32 out          MODE 1: fp32 out + fp32 X residual
// MODE 2: fp16 out, silu(half X)*acc   MODE 3: fp16 out plain
#define GST 3
template <int MODE>
__global__ __launch_bounds__(256, 2)
void hgemm_kernel(const __half* __restrict__ A, const __half* __restrict__ W,
                  const void* X, void* Cout, int M, int N, int K) {
    __shared__ __align__(16) __half sA[GST][128 * 32];
    __shared__ __align__(16) __half sB[GST][128 * 32];

    int tid  = threadIdx.x;
    int bm   = blockIdx.y * 128;
    int bn   = blockIdx.x * 128;
    int warp = tid >> 5;
    int lane = tid & 31;
    int wm   = (warp >> 1) * 32;
    int wn   = (warp & 1) * 64;

    uint32_t dstOff[2];
    int srow[2], su[2];
    #pragma unroll
    for (int j = 0; j < 2; j++) {
        int idx = tid + 256 * j;
        int row = idx >> 2, u = idx & 3;
        int uz  = u ^ ((row >> 1) & 3);
        dstOff[j] = (uint32_t)(row * 32 + uz * 8) * 2u;
        srow[j] = row; su[j] = u;
    }

    uint32_t aBase = (uint32_t)__cvta_generic_to_shared(&sA[0][0]);
    uint32_t bBase = (uint32_t)__cvta_generic_to_shared(&sB[0][0]);

    int l15 = lane & 15, lh = lane >> 4;
    uint32_t offA[2][2];
    #pragma unroll
    for (int q = 0; q < 2; q++)
        #pragma unroll
        for (int mt = 0; mt < 2; mt++) {
            int row = wm + mt * 16 + l15;
            int u   = 2 * q + lh;
            int uz  = u ^ ((row >> 1) & 3);
            offA[q][mt] = (uint32_t)(row * 32 + uz * 8) * 2u;
        }
    uint32_t offB[2][2][2];
    #pragma unroll
    for (int q = 0; q < 2; q++)
        #pragma unroll
        for (int kh = 0; kh < 2; kh++)
            #pragma unroll
            for (int gb = 0; gb < 2; gb++) {
                int row = wn + gb * 32 + lane;
                int u   = 2 * q + kh;
                int uz  = u ^ ((row >> 1) & 3);
                offB[q][kh][gb] = (uint32_t)(row * 32 + uz * 8) * 2u;
            }

    float acc[2][8][4];
    #pragma unroll
    for (int mt = 0; mt < 2; mt++)
        #pragma unroll
        for (int nt = 0; nt < 8; nt++)
            #pragma unroll
            for (int e = 0; e < 4; e++) acc[mt][nt][e] = 0.f;

    int NC = K >> 5;

    #pragma unroll
    for (int s = 0; s < 2; s++) {
        #pragma unroll
        for (int j = 0; j < 2; j++) {
            cp16(aBase + s * 8192u + dstOff[j],
                 A + (size_t)(bm + srow[j]) * K + s * 32 + su[j] * 8);
            cp16(bBase + s * 8192u + dstOff[j],
                 W + (size_t)(bn + srow[j]) * K + s * 32 + su[j] * 8);
        }
        asm volatile("cp.async.commit_group;" ::: "memory");
    }

    int st = 0, sn = 2;
    for (int ck = 0; ck < NC; ck++) {
        asm volatile("cp.async.wait_group 1;" ::: "memory");
        __syncthreads();

        uint32_t tA = aBase + st * 8192u;
        uint32_t tB = bBase + st * 8192u;
        #pragma unroll
        for (int q = 0; q < 2; q++) {
            uint32_t aR[2][4], bR[2][2][4];
            ldsm4(aR[0][0], aR[0][1], aR[0][2], aR[0][3], tA + offA[q][0]);
            ldsm4(aR[1][0], aR[1][1], aR[1][2], aR[1][3], tA + offA[q][1]);
            #pragma unroll
            for (int kh = 0; kh < 2; kh++)
                #pragma unroll
                for (int gb = 0; gb < 2; gb++)
                    ldsm4(bR[kh][gb][0], bR[kh][gb][1], bR[kh][gb][2], bR[kh][gb][3],
                          tB + offB[q][kh][gb]);
            #pragma unroll
            for (int mt = 0; mt < 2; mt++)
                #pragma unroll
                for (int nt = 0; nt < 8; nt++)
                    mma_f16(acc[mt][nt],
                            aR[mt][0], aR[mt][1], aR[mt][2], aR[mt][3],
                            bR[0][nt >> 2][nt & 3], bR[1][nt >> 2][nt & 3]);
        }

        int cn = ck + 2;
        if (cn < NC) {
            uint32_t nA = aBase + sn * 8192u;
            uint32_t nB = bBase + sn * 8192u;
            #pragma unroll
            for (int j = 0; j < 2; j++) {
                cp16(nA + dstOff[j],
                     A + (size_t)(bm + srow[j]) * K + cn * 32 + su[j] * 8);
                cp16(nB + dstOff[j],
                     W + (size_t)(bn + srow[j]) * K + cn * 32 + su[j] * 8);
            }
        }
        asm volatile("cp.async.commit_group;" ::: "memory");

        st = (st + 1 == GST) ? 0 : st + 1;
        sn = (sn + 1 == GST) ? 0 : sn + 1;
    }

    int g = lane >> 2;
    int t = lane & 3;
    #pragma unroll
    for (int mt = 0; mt < 2; mt++) {
        #pragma unroll
        for (int half = 0; half < 2; half++) {
            int row = bm + wm + mt * 16 + half * 8 + g;
            #pragma unroll
            for (int nt = 0; nt < 8; nt++) {
                int col = bn + wn + nt * 8 + 2 * t;
                float2 v;
                v.x = acc[mt][nt][half * 2 + 0];
                v.y = acc[mt][nt][half * 2 + 1];
                if (MODE == 1) {
                    float2 xv = *(const float2*)((const float*)X +
                                                 (size_t)row * N + col);
                    v.x += xv.x; v.y += xv.y;
                }
                if (MODE == 2) {
                    uint32_t xu = *(const uint32_t*)((const __half*)X +
                                                     (size_t)row * N + col);
                    __half2 xh = *(__half2*)&xu;
                    float ax = __low2float(xh), ay = __high2float(xh);
                    v.x *= ax / (1.f + expf(-ax));
                    v.y *= ay / (1.f + expf(-ay));
                }
                if (MODE == 2 || MODE == 3) {
                    __half2 hv = __floats2half2_rn(v.x, v.y);
                    *(uint32_t*)((__half*)Cout + (size_t)row * N + col) =
                        *(uint32_t*)&hv;
                } else {
                    *(float2*)((float*)Cout + (size_t)row * N + col) = v;
                }
            }
        }
    }
}

// ---------------- RoPE + split qkv(fp16) -> q,k fp16 [B,H,T,dh] -------------
#define Q_SCALE (0.125f * 1.44269504088896f)   // 1/sqrt(64) * log2(e)
__global__ void rope_split_h_kernel(const __half* __restrict__ qkv,
                                    __half* __restrict__ q,
                                    __half* __restrict__ k) {
    int idx = blockIdx.x * blockDim.x + threadIdx.x;
    int i = idx & 31;
    int h = (idx >> 5) & 15;
    int m = idx >> 9;
    int b = m >> 11;
    int t = m & 2047;

    const __half* base = qkv + (size_t)m * (3 * C_DIM) + h * DH + 2 * i;
    __half2 qv = *(const __half2*)(base);
    __half2 kv = *(const __half2*)(base + C_DIM);
    float q1 = __low2float(qv), q2 = __high2float(qv);
    float k1 = __low2float(kv), k2 = __high2float(kv);

    float freq = expf(-(2.0f * (float)i) * (1.0f / 64.0f) * 9.210340371976184f);
    float th = (float)t * freq;
    float s, c;
    sincosf(th, &s, &c);

    size_t o = ((size_t)(b * H_NUM + h) * T_LEN + t) * DH + 2 * i;
    __half2 qh = __floats2half2_rn((q1 * c - q2 * s) * Q_SCALE,
                                   (q1 * s + q2 * c) * Q_SCALE);
    __half2 kh = __floats2half2_rn(k1 * c - k2 * s, k1 * s + k2 * c);
    *(uint32_t*)(q + o) = *(uint32_t*)&qh;
    *(uint32_t*)(k + o) = *(uint32_t*)&kh;
}

// ---------------- V transpose: qkv(fp16) v-section -> [B,H,dh,T] fp16 -------
__global__ void vtrans_h_kernel(const __half* __restrict__ qkv,
                                __half* __restrict__ vt) {
    __shared__ __half s[64][68];
    int bh = blockIdx.y;
    int b  = bh >> 4;
    int h  = bh & 15;
    int t0 = blockIdx.x * 64;
    int tid = threadIdx.x;

    // load 64 tokens x 64 dims (each thread: 4 halves)
    for (int idx = tid; idx < 64 * 16; idx += 256) {
        int tok = idx >> 4, u = idx & 15;
        uint2 hv = *(const uint2*)(qkv + (size_t)(b * T_LEN + t0 + tok) * (3 * C_DIM)
                                   + 2 * C_DIM + h * DH + u * 4);
        *(uint2*)&s[tok][u * 4] = hv;
    }
    __syncthreads();
    for (int idx = tid; idx < 64 * 32; idx += 256) {
        int d = idx >> 5, tp = idx & 31;
        __half2 hv = __halves2half2(s[2 * tp][d], s[2 * tp + 1][d]);
        *(uint32_t*)(vt + ((size_t)bh * DH + d) * T_LEN + t0 + 2 * tp) =
            *(uint32_t*)&hv;
    }
}

// ---------------- fp16 causal flash attention (R14 proven) ------------------
#define HPAD 72
#define ONES16 0x3C003C00u
#define KV_TILE (64 * HPAD)
__global__ __launch_bounds__(128)
void attn_h_kernel(const __half* __restrict__ Q,
                   const __half* __restrict__ Kg,
                   const __half* __restrict__ Vt,
                   __half* __restrict__ O) {
    __shared__ __align__(16) __half sQ[64 * HPAD];     // later: P
    __shared__ __align__(16) __half sK[2][KV_TILE];
    __shared__ __align__(16) __half sV[2][KV_TILE];

    int bh   = blockIdx.y;
    int b    = bh >> 4;
    int head = bh & 15;
    int q0   = blockIdx.x * 64;
    int tid  = threadIdx.x;
    int warp = tid >> 5;
    int lane = tid & 31;
    int wm   = warp * 16;
    int g    = lane >> 2;
    int t    = lane & 3;
    int l15  = lane & 15;
    int lh   = lane >> 4;

    uint32_t qB = (uint32_t)__cvta_generic_to_shared(sQ);
    uint32_t kB = (uint32_t)__cvta_generic_to_shared(&sK[0][0]);
    uint32_t vB = (uint32_t)__cvta_generic_to_shared(&sV[0][0]);

    const __half* kg0 = Kg + (size_t)bh * T_LEN * DH;
    const __half* vg0 = Vt + (size_t)bh * DH * T_LEN;

    int cr[4], cu[4];
    uint32_t cOff[4];
    #pragma unroll
    for (int j = 0; j < 4; j++) {
        int idx = tid + 128 * j;
        cr[j] = idx >> 3; cu[j] = idx & 7;
        cOff[j] = (uint32_t)(cr[j] * HPAD + cu[j] * 8) * 2u;
    }

    const __half* qg = Q + ((size_t)bh * T_LEN + q0) * DH;
    #pragma unroll
    for (int idx = tid; idx < 512; idx += 128) {
        int r = idx >> 3, u = idx & 7;
        *(uint4*)&sQ[r * HPAD + u * 8] = *(const uint4*)(qg + r * DH + u * 8);
    }

    #pragma unroll
    for (int j = 0; j < 4; j++) {
        cp16(kB + cOff[j], kg0 + (size_t)cr[j] * DH + cu[j] * 8);
        cp16(vB + cOff[j], vg0 + (size_t)cr[j] * T_LEN + cu[j] * 8);
    }
    asm volatile("cp.async.commit_group;" ::: "memory");
    __syncthreads();

    uint32_t qf[4][4];
    #pragma unroll
    for (int kc = 0; kc < 4; kc++) {
        int row = wm + l15;
        int u   = kc * 2 + lh;
        ldsm4(qf[kc][0], qf[kc][1], qf[kc][2], qf[kc][3],
              qB + (uint32_t)(row * HPAD + u * 8) * 2u);
    }
    __syncthreads();   // sQ now reusable as P

    float accO[8][4];
    #pragma unroll
    for (int nt = 0; nt < 8; nt++)
        #pragma unroll
        for (int e = 0; e < 4; e++) accO[nt][e] = 0.f;
    float lacc[4] = {0.f, 0.f, 0.f, 0.f};
    float m0 = -1e30f, m1 = -1e30f;

    int r0 = q0 + wm + g;
    int r1 = r0 + 8;
    int prow0 = (wm + g) * HPAD;
    int prow1 = (wm + g + 8) * HPAD;

    int ntiles = q0 / 64 + 1;
    for (int kt = 0; kt < ntiles; kt++) {
        int st = kt & 1;
        bool more = (kt + 1) < ntiles;
        if (more) {
            int ks1 = (kt + 1) * 64;
            uint32_t kS = kB + (st ^ 1) * (KV_TILE * 2);
            uint32_t vS = vB + (st ^ 1) * (KV_TILE * 2);
            const __half* kbase = kg0 + (size_t)ks1 * DH;
            const __half* vbase = vg0 + ks1;
            #pragma unroll
            for (int j = 0; j < 4; j++) {
                cp16(kS + cOff[j], kbase + (size_t)cr[j] * DH + cu[j] * 8);
                cp16(vS + cOff[j], vbase + (size_t)cr[j] * T_LEN + cu[j] * 8);
            }
        }
        asm volatile("cp.async.commit_group;" ::: "memory");
        if (more)
            asm volatile("cp.async.wait_group 1;" ::: "memory");
        else
            asm volatile("cp.async.wait_group 0;" ::: "memory");
        __syncthreads();

        int ks = kt * 64;
        uint32_t kT = kB + st * (KV_TILE * 2);
        uint32_t vT = vB + st * (KV_TILE * 2);

        if (ks <= q0 + wm + 15) {
            float s[8][4];
            #pragma unroll
            for (int nt = 0; nt < 8; nt++)
                #pragma unroll
                for (int e = 0; e < 4; e++) s[nt][e] = 0.f;

            #pragma unroll
            for (int kc = 0; kc < 4; kc++) {
                uint32_t bR[2][2][4];
                #pragma unroll
                for (int kh = 0; kh < 2; kh++)
                    #pragma unroll
                    for (int gb = 0; gb < 2; gb++) {
                        int row = gb * 32 + lane;
                        int u   = kc * 2 + kh;
                        ldsm4(bR[kh][gb][0], bR[kh][gb][1],
                              bR[kh][gb][2], bR[kh][gb][3],
                              kT + (uint32_t)(row * HPAD + u * 8) * 2u);
                    }
                #pragma unroll
                for (int nt = 0; nt < 8; nt++)
                    mma_f16(s[nt], qf[kc][0], qf[kc][1], qf[kc][2], qf[kc][3],
                            bR[0][nt >> 2][nt & 3], bR[1][nt >> 2][nt & 3]);
            }

            if (ks + 63 > q0 + wm) {
                #pragma unroll
                for (int nt = 0; nt < 8; nt++) {
                    int kc = ks + nt * 8 + 2 * t;
                    if (kc     > r0) s[nt][0] = -1e30f;
                    if (kc + 1 > r0) s[nt][1] = -1e30f;
                    if (kc     > r1) s[nt][2] = -1e30f;
                    if (kc + 1 > r1) s[nt][3] = -1e30f;
                }
            }

            float tm0 = -1e30f, tm1 = -1e30f;
            #pragma unroll
            for (int nt = 0; nt < 8; nt++) {
                tm0 = fmaxf(tm0, fmaxf(s[nt][0], s[nt][1]));
                tm1 = fmaxf(tm1, fmaxf(s[nt][2], s[nt][3]));
            }
            tm0 = fmaxf(tm0, __shfl_xor_sync(0xffffffffu, tm0, 1));
            tm0 = fmaxf(tm0, __shfl_xor_sync(0xffffffffu, tm0, 2));
            tm1 = fmaxf(tm1, __shfl_xor_sync(0xffffffffu, tm1, 1));
            tm1 = fmaxf(tm1, __shfl_xor_sync(0xffffffffu, tm1, 2));

            float mn0 = fmaxf(m0, tm0), mn1 = fmaxf(m1, tm1);
            float c0 = exp2f(m0 - mn0), c1 = exp2f(m1 - mn1);
            m0 = mn0; m1 = mn1;

            #pragma unroll
            for (int nt = 0; nt < 8; nt++) {
                uint32_t ha, hb;
                asm("cvt.rn.f16x2.f32 %0, %1, %2;" : "=r"(ha)
                    : "f"(s[nt][1] - mn0), "f"(s[nt][0] - mn0));
                asm("cvt.rn.f16x2.f32 %0, %1, %2;" : "=r"(hb)
                    : "f"(s[nt][3] - mn1), "f"(s[nt][2] - mn1));
                asm("ex2.approx.f16x2 %0, %1;" : "=r"(ha) : "r"(ha));
                asm("ex2.approx.f16x2 %0, %1;" : "=r"(hb) : "r"(hb));
                int col = nt * 8 + 2 * t;
                *(uint32_t*)&sQ[prow0 + col] = ha;
                *(uint32_t*)&sQ[prow1 + col] = hb;
            }

            #pragma unroll
            for (int nt = 0; nt < 8; nt++) {
                accO[nt][0] *= c0; accO[nt][1] *= c0;
                accO[nt][2] *= c1; accO[nt][3] *= c1;
            }
            lacc[0] *= c0; lacc[1] *= c0;
            lacc[2] *= c1; lacc[3] *= c1;
            __syncwarp();

            #pragma unroll
            for (int kc = 0; kc < 4; kc++) {
                uint32_t aP[4];
                {
                    int row = wm + l15;
                    int u   = kc * 2 + lh;
                    ldsm4(aP[0], aP[1], aP[2], aP[3],
                          qB + (uint32_t)(row * HPAD + u * 8) * 2u);
                }
                mma_f16(lacc, aP[0], aP[1], aP[2], aP[3], ONES16, ONES16);
                uint32_t bV[2][2][4];
                #pragma unroll
                for (int kh = 0; kh < 2; kh++)
                    #pragma unroll
                    for (int gb = 0; gb < 2; gb++) {
                        int row = gb * 32 + lane;
                        int u   = kc * 2 + kh;
                        ldsm4(bV[kh][gb][0], bV[kh][gb][1],
                              bV[kh][gb][2], bV[kh][gb][3],
                              vT + (uint32_t)(row * HPAD + u * 8) * 2u);
                    }
                #pragma unroll
                for (int nt = 0; nt < 8; nt++)
                    mma_f16(accO[nt], aP[0], aP[1], aP[2], aP[3],
                            bV[0][nt >> 2][nt & 3], bV[1][nt >> 2][nt & 3]);
            }
        }
        __syncthreads();
    }

    float inv0 = 1.f / lacc[0], inv1 = 1.f / lacc[2];
    __half* o0 = O + ((size_t)(b * T_LEN + r0)) * C_DIM + head * DH;
    __half* o1 = O + ((size_t)(b * T_LEN + r1)) * C_DIM + head * DH;
    #pragma unroll
    for (int nt = 0; nt < 8; nt++) {
        int col = nt * 8 + 2 * t;
        __half2 h0 = __floats2half2_rn(accO[nt][0] * inv0, accO[nt][1] * inv0);
        __half2 h1 = __floats2half2_rn(accO[nt][2] * inv1, accO[nt][3] * inv1);
        *(uint32_t*)(o0 + col) = *(uint32_t*)&h0;
        *(uint32_t*)(o1 + col) = *(uint32_t*)&h1;
    }
}

// ---------------- launch ----------------------------------------------------
extern "C" void kernel_launch(void* const* d_in, const int* in_sizes, int n_in,
                              void* d_out, int out_size) {
    const float* x      = (const float*)d_in[0];
    const float* w_qkv  = (const float*)d_in[1];
    const float* w_proj = (const float*)d_in[2];
    const float* g1     = (const float*)d_in[3];
    const float* g2     = (const float*)d_in[4];
    const float* w1     = (const float*)d_in[5];
    const float* w2     = (const float*)d_in[6];
    const float* w3     = (const float*)d_in[7];
    float* out = (float*)d_out;

    __half *p_h16, *p_qkv16, *p_q16, *p_k16, *p_v16, *p_o16, *p_ffa, *p_ff16, *p_w16;
    float  *p_x1;
    cudaGetSymbolAddress((void**)&p_h16,   g_h16);
    cudaGetSymbolAddress((void**)&p_qkv16, g_qkv16);
    cudaGetSymbolAddress((void**)&p_q16,   g_q16);
    cudaGetSymbolAddress((void**)&p_k16,   g_k16);
    cudaGetSymbolAddress((void**)&p_v16,   g_v16);
    cudaGetSymbolAddress((void**)&p_o16,   g_o16);
    cudaGetSymbolAddress((void**)&p_x1,    g_x1);
    cudaGetSymbolAddress((void**)&p_ffa,   g_ffa);
    cudaGetSymbolAddress((void**)&p_ff16,  g_ff16);
    cudaGetSymbolAddress((void**)&p_w16,   g_w16);

    __half* w_qkv16  = p_w16;
    __half* w_proj16 = w_qkv16  + 3 * C_DIM * C_DIM;
    __half* w116     = w_proj16 + C_DIM * C_DIM;
    __half* w216     = w116     + 4 * C_DIM * C_DIM;
    __half* w316     = w216     + 4 * C_DIM * C_DIM;

    f2h_all_kernel<<<2048, 256>>>(w_qkv, w_proj, w1, w2, w3, p_w16);

    rmsnorm_h_kernel<<<M_TOK, 256>>>(x, g1, p_h16);
    // qkv (fp16 out)
    hgemm_kernel<3><<<dim3(3 * C_DIM / 128, M_TOK / 128), 256>>>(
        p_h16, w_qkv16, nullptr, p_qkv16, M_TOK, 3 * C_DIM, C_DIM);
    rope_split_h_kernel<<<(M_TOK * H_NUM * 32) / 256, 256>>>(p_qkv16, p_q16, p_k16);
    vtrans_h_kernel<<<dim3(T_LEN / 64, B_NUM * H_NUM), 256>>>(p_qkv16, p_v16);
    attn_h_kernel<<<dim3(T_LEN / 64, B_NUM * H_NUM), 128>>>(
        p_q16, p_k16, p_v16, p_o16);
    hgemm_kernel<1><<<dim3(C_DIM / 128, M_TOK / 128), 256>>>(
        p_o16, w_proj16, x, p_x1, M_TOK, C_DIM, C_DIM);
    rmsnorm_h_kernel<<<M_TOK, 256>>>(p_x1, g2, p_h16);
    // a = h2 @ w1^T (fp16 out)
    hgemm_kernel<3><<<dim3(FF_DIM / 128, M_TOK / 128), 256>>>(
        p_h16, w116, nullptr, p_ffa, M_TOK, FF_DIM, C_DIM);
    // ff = silu(a) * (h2 @ w3^T) (fp16 out, half X)
    hgemm_kernel<2><<<dim3(FF_DIM / 128, M_TOK / 128), 256>>>(
        p_h16, w316, p_ffa, p_ff16, M_TOK, FF_DIM, C_DIM);
    hgemm_kernel<1><<<dim3(C_DIM / 128, M_TOK / 128), 256>>>(
        p_ff16, w216, p_x1, out, M_TOK, C_DIM, FF_DIM);
}

// round 16
// speedup vs baseline: 1.0987x; 1.0020x over previous
#include <cuda_runtime.h>
#include <cuda_fp16.h>
#include <math.h>
#include <stdint.h>

#define C_DIM   1024
#define H_NUM   16
#define DH      64
#define FF_DIM  4096
#define B_NUM   2
#define T_LEN   2048
#define M_TOK   4096   // B*T

// ---------------- scratch (device globals; no allocation allowed) ----------
__device__ __half g_h16 [M_TOK * C_DIM];       // rmsnorm out (fp16)
__device__ __half g_qkv16[M_TOK * 3 * C_DIM];  // qkv (fp16)
__device__ __half g_q16 [M_TOK * C_DIM];       // [B,H,T,dh] (pre-scaled fp16)
__device__ __half g_k16 [M_TOK * C_DIM];       // [B,H,T,dh] fp16
__device__ __half g_v16 [M_TOK * C_DIM];       // [B,H,dh,T] fp16 (transposed)
__device__ __half g_o16 [M_TOK * C_DIM];       // attention out (fp16)
__device__ float  g_x1  [M_TOK * C_DIM];
__device__ __half g_ff16[M_TOK * FF_DIM];      // silu(a)*b (fp16)
__device__ __half g_w16 [16 * C_DIM * C_DIM];  // all weights fp16 (16M halves)

// ---------------- helpers ----------------------------------------------------
__device__ __forceinline__ void mma_f16(float c[4],
                                        uint32_t a0, uint32_t a1, uint32_t a2, uint32_t a3,
                                        uint32_t b0, uint32_t b1) {
    asm volatile(
        "mma.sync.aligned.m16n8k16.row.col.f32.f16.f16.f32 "
        "{%0,%1,%2,%3}, {%4,%5,%6,%7}, {%8,%9}, {%0,%1,%2,%3};\n"
        : "+f"(c[0]), "+f"(c[1]), "+f"(c[2]), "+f"(c[3])
        : "r"(a0), "r"(a1), "r"(a2), "r"(a3), "r"(b0), "r"(b1));
}
__device__ __forceinline__ void ldsm4(uint32_t& r0, uint32_t& r1,
                                      uint32_t& r2, uint32_t& r3, uint32_t addr) {
    asm volatile("ldmatrix.sync.aligned.m8n8.x4.shared.b16 {%0,%1,%2,%3}, [%4];"
                 : "=r"(r0), "=r"(r1), "=r"(r2), "=r"(r3) : "r"(addr));
}
__device__ __forceinline__ void cp16(uint32_t dst, const void* src) {
    asm volatile("cp.async.cg.shared.global [%0], [%1], 16;" :: "r"(dst), "l"(src));
}

// ---------------- fused fp32 -> fp16 weight convert (single launch) ---------
__global__ void f2h_all_kernel(const float* __restrict__ w_qkv,
                               const float* __restrict__ w_proj,
                               const float* __restrict__ w1,
                               const float* __restrict__ w2,
                               const float* __restrict__ w3,
                               __half* __restrict__ out) {
    int unit = blockIdx.x >> 7;
    const float* src;
    if (unit < 3)       src = w_qkv  + ((size_t)unit << 20);
    else if (unit < 4)  src = w_proj;
    else if (unit < 8)  src = w1 + ((size_t)(unit - 4) << 20);
    else if (unit < 12) src = w2 + ((size_t)(unit - 8) << 20);
    else                src = w3 + ((size_t)(unit - 12) << 20);
    __half* dst = out + ((size_t)unit << 20);

    size_t local = (size_t)(blockIdx.x & 127) * 8192 + threadIdx.x * 8;
    #pragma unroll
    for (int j = 0; j < 4; j++) {
        size_t idx = local + (size_t)j * 2048;
        float4 a = *(const float4*)(src + idx);
        float4 b = *(const float4*)(src + idx + 4);
        __half2 h0 = __floats2half2_rn(a.x, a.y);
        __half2 h1 = __floats2half2_rn(a.z, a.w);
        __half2 h2 = __floats2half2_rn(b.x, b.y);
        __half2 h3 = __floats2half2_rn(b.z, b.w);
        uint4 u;
        u.x = *(uint32_t*)&h0; u.y = *(uint32_t*)&h1;
        u.z = *(uint32_t*)&h2; u.w = *(uint32_t*)&h3;
        *(uint4*)(dst + idx) = u;
    }
}

// ---------------- RMSNorm -> fp16 --------------------------------------------
__global__ void rmsnorm_h_kernel(const float* __restrict__ x,
                                 const float* __restrict__ g,
                                 __half* __restrict__ y) {
    int row = blockIdx.x;
    int tid = threadIdx.x;
    const float4* xr = (const float4*)(x + (size_t)row * C_DIM);
    const float4* gr = (const float4*)g;

    float4 xv = xr[tid];
    float ss = xv.x*xv.x + xv.y*xv.y + xv.z*xv.z + xv.w*xv.w;
    #pragma unroll
    for (int off = 16; off > 0; off >>= 1)
        ss += __shfl_xor_sync(0xffffffffu, ss, off);
    __shared__ float red[8];
    if ((tid & 31) == 0) red[tid >> 5] = ss;
    __syncthreads();
    float tot = 0.f;
    #pragma unroll
    for (int i = 0; i < 8; i++) tot += red[i];
    float inv = rsqrtf(tot * (1.0f / C_DIM) + 1e-5f);

    float4 gv = gr[tid];
    __half2 h0 = __floats2half2_rn(xv.x * gv.x * inv, xv.y * gv.y * inv);
    __half2 h1 = __floats2half2_rn(xv.z * gv.z * inv, xv.w * gv.w * inv);
    uint2 u;
    u.x = *(uint32_t*)&h0; u.y = *(uint32_t*)&h1;
    *(uint2*)(y + (size_t)row * C_DIM + tid * 4) = u;
}

// ---------------- fp16 tensor-core GEMM (k32, 3-stage cp.async) -------------
// MODE 0: fp32 out   MODE 1: fp32 out + fp32 X residual   MODE 3: fp16 out
#define GST 3
template <int MODE>
__global__ __launch_bounds__(256, 2)
void hgemm_kernel(const __half* __restrict__ A, const __half* __restrict__ W,
                  const void* X, void* Cout, int M, int N, int K) {
    __shared__ __align__(16) __half sA[GST][128 * 32];
    __shared__ __align__(16) __half sB[GST][128 * 32];

    int tid  = threadIdx.x;
    int bm   = blockIdx.y * 128;
    int bn   = blockIdx.x * 128;
    int warp = tid >> 5;
    int lane = tid & 31;
    int wm   = (warp >> 1) * 32;
    int wn   = (warp & 1) * 64;

    uint32_t dstOff[2];
    int srow[2], su[2];
    #pragma unroll
    for (int j = 0; j < 2; j++) {
        int idx = tid + 256 * j;
        int row = idx >> 2, u = idx & 3;
        int uz  = u ^ ((row >> 1) & 3);
        dstOff[j] = (uint32_t)(row * 32 + uz * 8) * 2u;
        srow[j] = row; su[j] = u;
    }

    uint32_t aBase = (uint32_t)__cvta_generic_to_shared(&sA[0][0]);
    uint32_t bBase = (uint32_t)__cvta_generic_to_shared(&sB[0][0]);

    int l15 = lane & 15, lh = lane >> 4;
    uint32_t offA[2][2];
    #pragma unroll
    for (int q = 0; q < 2; q++)
        #pragma unroll
        for (int mt = 0; mt < 2; mt++) {
            int row = wm + mt * 16 + l15;
            int u   = 2 * q + lh;
            int uz  = u ^ ((row >> 1) & 3);
            offA[q][mt] = (uint32_t)(row * 32 + uz * 8) * 2u;
        }
    uint32_t offB[2][2][2];
    #pragma unroll
    for (int q = 0; q < 2; q++)
        #pragma unroll
        for (int kh = 0; kh < 2; kh++)
            #pragma unroll
            for (int gb = 0; gb < 2; gb++) {
                int row = wn + gb * 32 + lane;
                int u   = 2 * q + kh;
                int uz  = u ^ ((row >> 1) & 3);
                offB[q][kh][gb] = (uint32_t)(row * 32 + uz * 8) * 2u;
            }

    float acc[2][8][4];
    #pragma unroll
    for (int mt = 0; mt < 2; mt++)
        #pragma unroll
        for (int nt = 0; nt < 8; nt++)
            #pragma unroll
            for (int e = 0; e < 4; e++) acc[mt][nt][e] = 0.f;

    int NC = K >> 5;

    #pragma unroll
    for (int s = 0; s < 2; s++) {
        #pragma unroll
        for (int j = 0; j < 2; j++) {
            cp16(aBase + s * 8192u + dstOff[j],
                 A + (size_t)(bm + srow[j]) * K + s * 32 + su[j] * 8);
            cp16(bBase + s * 8192u + dstOff[j],
                 W + (size_t)(bn + srow[j]) * K + s * 32 + su[j] * 8);
        }
        asm volatile("cp.async.commit_group;" ::: "memory");
    }

    int st = 0, sn = 2;
    for (int ck = 0; ck < NC; ck++) {
        asm volatile("cp.async.wait_group 1;" ::: "memory");
        __syncthreads();

        uint32_t tA = aBase + st * 8192u;
        uint32_t tB = bBase + st * 8192u;
        #pragma unroll
        for (int q = 0; q < 2; q++) {
            uint32_t aR[2][4], bR[2][2][4];
            ldsm4(aR[0][0], aR[0][1], aR[0][2], aR[0][3], tA + offA[q][0]);
            ldsm4(aR[1][0], aR[1][1], aR[1][2], aR[1][3], tA + offA[q][1]);
            #pragma unroll
            for (int kh = 0; kh < 2; kh++)
                #pragma unroll
                for (int gb = 0; gb < 2; gb++)
                    ldsm4(bR[kh][gb][0], bR[kh][gb][1], bR[kh][gb][2], bR[kh][gb][3],
                          tB + offB[q][kh][gb]);
            #pragma unroll
            for (int mt = 0; mt < 2; mt++)
                #pragma unroll
                for (int nt = 0; nt < 8; nt++)
                    mma_f16(acc[mt][nt],
                            aR[mt][0], aR[mt][1], aR[mt][2], aR[mt][3],
                            bR[0][nt >> 2][nt & 3], bR[1][nt >> 2][nt & 3]);
        }

        int cn = ck + 2;
        if (cn < NC) {
            uint32_t nA = aBase + sn * 8192u;
            uint32_t nB = bBase + sn * 8192u;
            #pragma unroll
            for (int j = 0; j < 2; j++) {
                cp16(nA + dstOff[j],
                     A + (size_t)(bm + srow[j]) * K + cn * 32 + su[j] * 8);
                cp16(nB + dstOff[j],
                     W + (size_t)(bn + srow[j]) * K + cn * 32 + su[j] * 8);
            }
        }
        asm volatile("cp.async.commit_group;" ::: "memory");

        st = (st + 1 == GST) ? 0 : st + 1;
        sn = (sn + 1 == GST) ? 0 : sn + 1;
    }

    int g = lane >> 2;
    int t = lane & 3;
    #pragma unroll
    for (int mt = 0; mt < 2; mt++) {
        #pragma unroll
        for (int half = 0; half < 2; half++) {
            int row = bm + wm + mt * 16 + half * 8 + g;
            #pragma unroll
            for (int nt = 0; nt < 8; nt++) {
                int col = bn + wn + nt * 8 + 2 * t;
                float2 v;
                v.x = acc[mt][nt][half * 2 + 0];
                v.y = acc[mt][nt][half * 2 + 1];
                if (MODE == 1) {
                    float2 xv = *(const float2*)((const float*)X +
                                                 (size_t)row * N + col);
                    v.x += xv.x; v.y += xv.y;
                }
                if (MODE == 3) {
                    __half2 hv = __floats2half2_rn(v.x, v.y);
                    *(uint32_t*)((__half*)Cout + (size_t)row * N + col) =
                        *(uint32_t*)&hv;
                } else {
                    *(float2*)((float*)Cout + (size_t)row * N + col) = v;
                }
            }
        }
    }
}

// ---------------- fused FFN gate: ff = silu(h@w1^T) * (h@w3^T) --------------
// Block outputs 128(M) x 64(N). Warps 0-3: w1 (a); warps 4-7: w3 (b).
// Same 32x64 warp tile / ldsm / mma / 3-stage cp.async as hgemm.
__global__ __launch_bounds__(256, 2)
void ffgate_kernel(const __half* __restrict__ A, const __half* __restrict__ W1,
                   const __half* __restrict__ W3, __half* __restrict__ Cout,
                   int M, int N, int K) {
    __shared__ __align__(16) char smemraw[49152];
    __half* sA = (__half*)smemraw;                 // 3 x 8KB
    uint32_t aBase  = (uint32_t)__cvta_generic_to_shared(sA);
    uint32_t b1Base = aBase + 24576u;              // 3 x 4KB
    uint32_t b2Base = aBase + 36864u;              // 3 x 4KB

    int tid  = threadIdx.x;
    int bm   = blockIdx.y * 128;
    int bn   = blockIdx.x * 64;
    int warp = tid >> 5;
    int lane = tid & 31;
    int halfw = warp >> 2;           // 0 = w1(a), 1 = w3(b)
    int wm    = (warp & 3) * 32;

    // A store mapping (2 units/thread)
    uint32_t dstOffA[2];
    int arow[2], au[2];
    #pragma unroll
    for (int j = 0; j < 2; j++) {
        int idx = tid + 256 * j;
        int row = idx >> 2, u = idx & 3;
        int uz  = u ^ ((row >> 1) & 3);
        dstOffA[j] = (uint32_t)(row * 32 + uz * 8) * 2u;
        arow[j] = row; au[j] = u;
    }
    // B store mapping (1 unit per matrix per thread; 64 rows x 4 units)
    int brow = tid >> 2, bu = tid & 3;
    uint32_t dstOffB = (uint32_t)(brow * 32 + (bu ^ ((brow >> 1) & 3)) * 8) * 2u;

    int l15 = lane & 15, lh = lane >> 4;
    uint32_t offA[2][2];
    #pragma unroll
    for (int q = 0; q < 2; q++)
        #pragma unroll
        for (int mt = 0; mt < 2; mt++) {
            int row = wm + mt * 16 + l15;
            int u   = 2 * q + lh;
            int uz  = u ^ ((row >> 1) & 3);
            offA[q][mt] = (uint32_t)(row * 32 + uz * 8) * 2u;
        }
    uint32_t offB[2][2][2];
    #pragma unroll
    for (int q = 0; q < 2; q++)
        #pragma unroll
        for (int kh = 0; kh < 2; kh++)
            #pragma unroll
            for (int gb = 0; gb < 2; gb++) {
                int row = gb * 32 + lane;
                int u   = 2 * q + kh;
                int uz  = u ^ ((row >> 1) & 3);
                offB[q][kh][gb] = (uint32_t)(row * 32 + uz * 8) * 2u;
            }
    uint32_t bSel = halfw ? b2Base : b1Base;

    float acc[2][8][4];
    #pragma unroll
    for (int mt = 0; mt < 2; mt++)
        #pragma unroll
        for (int nt = 0; nt < 8; nt++)
            #pragma unroll
            for (int e = 0; e < 4; e++) acc[mt][nt][e] = 0.f;

    int NC = K >> 5;

    #pragma unroll
    for (int s = 0; s < 2; s++) {
        #pragma unroll
        for (int j = 0; j < 2; j++)
            cp16(aBase + s * 8192u + dstOffA[j],
                 A + (size_t)(bm + arow[j]) * K + s * 32 + au[j] * 8);
        cp16(b1Base + s * 4096u + dstOffB,
             W1 + (size_t)(bn + brow) * K + s * 32 + bu * 8);
        cp16(b2Base + s * 4096u + dstOffB,
             W3 + (size_t)(bn + brow) * K + s * 32 + bu * 8);
        asm volatile("cp.async.commit_group;" ::: "memory");
    }

    int st = 0, sn = 2;
    for (int ck = 0; ck < NC; ck++) {
        asm volatile("cp.async.wait_group 1;" ::: "memory");
        __syncthreads();

        uint32_t tA = aBase + st * 8192u;
        uint32_t tB = bSel + st * 4096u;
        #pragma unroll
        for (int q = 0; q < 2; q++) {
            uint32_t aR[2][4], bR[2][2][4];
            ldsm4(aR[0][0], aR[0][1], aR[0][2], aR[0][3], tA + offA[q][0]);
            ldsm4(aR[1][0], aR[1][1], aR[1][2], aR[1][3], tA + offA[q][1]);
            #pragma unroll
            for (int kh = 0; kh < 2; kh++)
                #pragma unroll
                for (int gb = 0; gb < 2; gb++)
                    ldsm4(bR[kh][gb][0], bR[kh][gb][1], bR[kh][gb][2], bR[kh][gb][3],
                          tB + offB[q][kh][gb]);
            #pragma unroll
            for (int mt = 0; mt < 2; mt++)
                #pragma unroll
                for (int nt = 0; nt < 8; nt++)
                    mma_f16(acc[mt][nt],
                            aR[mt][0], aR[mt][1], aR[mt][2], aR[mt][3],
                            bR[0][nt >> 2][nt & 3], bR[1][nt >> 2][nt & 3]);
        }

        int cn = ck + 2;
        if (cn < NC) {
            uint32_t nst = (uint32_t)sn;
            #pragma unroll
            for (int j = 0; j < 2; j++)
                cp16(aBase + nst * 8192u + dstOffA[j],
                     A + (size_t)(bm + arow[j]) * K + cn * 32 + au[j] * 8);
            cp16(b1Base + nst * 4096u + dstOffB,
                 W1 + (size_t)(bn + brow) * K + cn * 32 + bu * 8);
            cp16(b2Base + nst * 4096u + dstOffB,
                 W3 + (size_t)(bn + brow) * K + cn * 32 + bu * 8);
        }
        asm volatile("cp.async.commit_group;" ::: "memory");

        st = (st + 1 == GST) ? 0 : st + 1;
        sn = (sn + 1 == GST) ? 0 : sn + 1;
    }

    // epilogue: exchange silu(a) through smem (aliases dead stage memory)
    asm volatile("cp.async.wait_group 0;" ::: "memory");
    __syncthreads();
    float* sX = (float*)smemraw;   // 128 x 64 floats = 32 KB

    int g = lane >> 2;
    int t = lane & 3;
    if (halfw == 0) {
        #pragma unroll
        for (int mt = 0; mt < 2; mt++)
            #pragma unroll
            for (int hh = 0; hh < 2; hh++) {
                int row = wm + mt * 16 + hh * 8 + g;
                #pragma unroll
                for (int nt = 0; nt < 8; nt++) {
                    int col = nt * 8 + 2 * t;
                    float ax = acc[mt][nt][hh * 2 + 0];
                    float ay = acc[mt][nt][hh * 2 + 1];
                    float2 v;
                    v.x = ax / (1.f + expf(-ax));
                    v.y = ay / (1.f + expf(-ay));
                    *(float2*)&sX[row * 64 + col] = v;
                }
            }
    }
    __syncthreads();
    if (halfw == 1) {
        #pragma unroll
        for (int mt = 0; mt < 2; mt++)
            #pragma unroll
            for (int hh = 0; hh < 2; hh++) {
                int row = wm + mt * 16 + hh * 8 + g;
                #pragma unroll
                for (int nt = 0; nt < 8; nt++) {
                    int col = nt * 8 + 2 * t;
                    float2 sa = *(const float2*)&sX[row * 64 + col];
                    __half2 hv = __floats2half2_rn(
                        acc[mt][nt][hh * 2 + 0] * sa.x,
                        acc[mt][nt][hh * 2 + 1] * sa.y);
                    *(uint32_t*)(Cout + (size_t)(bm + row) * N + bn + col) =
                        *(uint32_t*)&hv;
                }
            }
    }
}

// ---------------- RoPE + split qkv(fp16) -> q,k fp16 [B,H,T,dh] -------------
#define Q_SCALE (0.125f * 1.44269504088896f)   // 1/sqrt(64) * log2(e)
__global__ void rope_split_h_kernel(const __half* __restrict__ qkv,
                                    __half* __restrict__ q,
                                    __half* __restrict__ k) {
    int idx = blockIdx.x * blockDim.x + threadIdx.x;
    int i = idx & 31;
    int h = (idx >> 5) & 15;
    int m = idx >> 9;
    int b = m >> 11;
    int t = m & 2047;

    const __half* base = qkv + (size_t)m * (3 * C_DIM) + h * DH + 2 * i;
    __half2 qv = *(const __half2*)(base);
    __half2 kv = *(const __half2*)(base + C_DIM);
    float q1 = __low2float(qv), q2 = __high2float(qv);
    float k1 = __low2float(kv), k2 = __high2float(kv);

    float freq = expf(-(2.0f * (float)i) * (1.0f / 64.0f) * 9.210340371976184f);
    float th = (float)t * freq;
    float s, c;
    sincosf(th, &s, &c);

    size_t o = ((size_t)(b * H_NUM + h) * T_LEN + t) * DH + 2 * i;
    __half2 qh = __floats2half2_rn((q1 * c - q2 * s) * Q_SCALE,
                                   (q1 * s + q2 * c) * Q_SCALE);
    __half2 kh = __floats2half2_rn(k1 * c - k2 * s, k1 * s + k2 * c);
    *(uint32_t*)(q + o) = *(uint32_t*)&qh;
    *(uint32_t*)(k + o) = *(uint32_t*)&kh;
}

// ---------------- V transpose: qkv(fp16) v-section -> [B,H,dh,T] fp16 -------
__global__ void vtrans_h_kernel(const __half* __restrict__ qkv,
                                __half* __restrict__ vt) {
    __shared__ __half s[64][68];
    int bh = blockIdx.y;
    int b  = bh >> 4;
    int h  = bh & 15;
    int t0 = blockIdx.x * 64;
    int tid = threadIdx.x;

    for (int idx = tid; idx < 64 * 16; idx += 256) {
        int tok = idx >> 4, u = idx & 15;
        uint2 hv = *(const uint2*)(qkv + (size_t)(b * T_LEN + t0 + tok) * (3 * C_DIM)
                                   + 2 * C_DIM + h * DH + u * 4);
        *(uint2*)&s[tok][u * 4] = hv;
    }
    __syncthreads();
    for (int idx = tid; idx < 64 * 32; idx += 256) {
        int d = idx >> 5, tp = idx & 31;
        __half2 hv = __halves2half2(s[2 * tp][d], s[2 * tp + 1][d]);
        *(uint32_t*)(vt + ((size_t)bh * DH + d) * T_LEN + t0 + 2 * tp) =
            *(uint32_t*)&hv;
    }
}

// ---------------- fp16 causal flash attention (R14 proven) ------------------
#define HPAD 72
#define ONES16 0x3C003C00u
#define KV_TILE (64 * HPAD)
__global__ __launch_bounds__(128)
void attn_h_kernel(const __half* __restrict__ Q,
                   const __half* __restrict__ Kg,
                   const __half* __restrict__ Vt,
                   __half* __restrict__ O) {
    __shared__ __align__(16) __half sQ[64 * HPAD];     // later: P
    __shared__ __align__(16) __half sK[2][KV_TILE];
    __shared__ __align__(16) __half sV[2][KV_TILE];

    int bh   = blockIdx.y;
    int b    = bh >> 4;
    int head = bh & 15;
    int q0   = blockIdx.x * 64;
    int tid  = threadIdx.x;
    int warp = tid >> 5;
    int lane = tid & 31;
    int wm   = warp * 16;
    int g    = lane >> 2;
    int t    = lane & 3;
    int l15  = lane & 15;
    int lh   = lane >> 4;

    uint32_t qB = (uint32_t)__cvta_generic_to_shared(sQ);
    uint32_t kB = (uint32_t)__cvta_generic_to_shared(&sK[0][0]);
    uint32_t vB = (uint32_t)__cvta_generic_to_shared(&sV[0][0]);

    const __half* kg0 = Kg + (size_t)bh * T_LEN * DH;
    const __half* vg0 = Vt + (size_t)bh * DH * T_LEN;

    int cr[4], cu[4];
    uint32_t cOff[4];
    #pragma unroll
    for (int j = 0; j < 4; j++) {
        int idx = tid + 128 * j;
        cr[j] = idx >> 3; cu[j] = idx & 7;
        cOff[j] = (uint32_t)(cr[j] * HPAD + cu[j] * 8) * 2u;
    }

    const __half* qg = Q + ((size_t)bh * T_LEN + q0) * DH;
    #pragma unroll
    for (int idx = tid; idx < 512; idx += 128) {
        int r = idx >> 3, u = idx & 7;
        *(uint4*)&sQ[r * HPAD + u * 8] = *(const uint4*)(qg + r * DH + u * 8);
    }

    #pragma unroll
    for (int j = 0; j < 4; j++) {
        cp16(kB + cOff[j], kg0 + (size_t)cr[j] * DH + cu[j] * 8);
        cp16(vB + cOff[j], vg0 + (size_t)cr[j] * T_LEN + cu[j] * 8);
    }
    asm volatile("cp.async.commit_group;" ::: "memory");
    __syncthreads();

    uint32_t qf[4][4];
    #pragma unroll
    for (int kc = 0; kc < 4; kc++) {
        int row = wm + l15;
        int u   = kc * 2 + lh;
        ldsm4(qf[kc][0], qf[kc][1], qf[kc][2], qf[kc][3],
              qB + (uint32_t)(row * HPAD + u * 8) * 2u);
    }
    __syncthreads();   // sQ now reusable as P

    float accO[8][4];
    #pragma unroll
    for (int nt = 0; nt < 8; nt++)
        #pragma unroll
        for (int e = 0; e < 4; e++) accO[nt][e] = 0.f;
    float lacc[4] = {0.f, 0.f, 0.f, 0.f};
    float m0 = -1e30f, m1 = -1e30f;

    int r0 = q0 + wm + g;
    int r1 = r0 + 8;
    int prow0 = (wm + g) * HPAD;
    int prow1 = (wm + g + 8) * HPAD;

    int ntiles = q0 / 64 + 1;
    for (int kt = 0; kt < ntiles; kt++) {
        int st = kt & 1;
        bool more = (kt + 1) < ntiles;
        if (more) {
            int ks1 = (kt + 1) * 64;
            uint32_t kS = kB + (st ^ 1) * (KV_TILE * 2);
            uint32_t vS = vB + (st ^ 1) * (KV_TILE * 2);
            const __half* kbase = kg0 + (size_t)ks1 * DH;
            const __half* vbase = vg0 + ks1;
            #pragma unroll
            for (int j = 0; j < 4; j++) {
                cp16(kS + cOff[j], kbase + (size_t)cr[j] * DH + cu[j] * 8);
                cp16(vS + cOff[j], vbase + (size_t)cr[j] * T_LEN + cu[j] * 8);
            }
        }
        asm volatile("cp.async.commit_group;" ::: "memory");
        if (more)
            asm volatile("cp.async.wait_group 1;" ::: "memory");
        else
            asm volatile("cp.async.wait_group 0;" ::: "memory");
        __syncthreads();

        int ks = kt * 64;
        uint32_t kT = kB + st * (KV_TILE * 2);
        uint32_t vT = vB + st * (KV_TILE * 2);

        if (ks <= q0 + wm + 15) {
            float s[8][4];
            #pragma unroll
            for (int nt = 0; nt < 8; nt++)
                #pragma unroll
                for (int e = 0; e < 4; e++) s[nt][e] = 0.f;

            #pragma unroll
            for (int kc = 0; kc < 4; kc++) {
                uint32_t bR[2][2][4];
                #pragma unroll
                for (int kh = 0; kh < 2; kh++)
                    #pragma unroll
                    for (int gb = 0; gb < 2; gb++) {
                        int row = gb * 32 + lane;
                        int u   = kc * 2 + kh;
                        ldsm4(bR[kh][gb][0], bR[kh][gb][1],
                              bR[kh][gb][2], bR[kh][gb][3],
                              kT + (uint32_t)(row * HPAD + u * 8) * 2u);
                    }
                #pragma unroll
                for (int nt = 0; nt < 8; nt++)
                    mma_f16(s[nt], qf[kc][0], qf[kc][1], qf[kc][2], qf[kc][3],
                            bR[0][nt >> 2][nt & 3], bR[1][nt >> 2][nt & 3]);
            }

            if (ks + 63 > q0 + wm) {
                #pragma unroll
                for (int nt = 0; nt < 8; nt++) {
                    int kc = ks + nt * 8 + 2 * t;
                    if (kc     > r0) s[nt][0] = -1e30f;
                    if (kc + 1 > r0) s[nt][1] = -1e30f;
                    if (kc     > r1) s[nt][2] = -1e30f;
                    if (kc + 1 > r1) s[nt][3] = -1e30f;
                }
            }

            float tm0 = -1e30f, tm1 = -1e30f;
            #pragma unroll
            for (int nt = 0; nt < 8; nt++) {
                tm0 = fmaxf(tm0, fmaxf(s[nt][0], s[nt][1]));
                tm1 = fmaxf(tm1, fmaxf(s[nt][2], s[nt][3]));
            }
            tm0 = fmaxf(tm0, __shfl_xor_sync(0xffffffffu, tm0, 1));
            tm0 = fmaxf(tm0, __shfl_xor_sync(0xffffffffu, tm0, 2));
            tm1 = fmaxf(tm1, __shfl_xor_sync(0xffffffffu, tm1, 1));
            tm1 = fmaxf(tm1, __shfl_xor_sync(0xffffffffu, tm1, 2));

            float mn0 = fmaxf(m0, tm0), mn1 = fmaxf(m1, tm1);
            float c0 = exp2f(m0 - mn0), c1 = exp2f(m1 - mn1);
            m0 = mn0; m1 = mn1;

            #pragma unroll
            for (int nt = 0; nt < 8; nt++) {
                uint32_t ha, hb;
                asm("cvt.rn.f16x2.f32 %0, %1, %2;" : "=r"(ha)
                    : "f"(s[nt][1] - mn0), "f"(s[nt][0] - mn0));
                asm("cvt.rn.f16x2.f32 %0, %1, %2;" : "=r"(hb)
                    : "f"(s[nt][3] - mn1), "f"(s[nt][2] - mn1));
                asm("ex2.approx.f16x2 %0, %1;" : "=r"(ha) : "r"(ha));
                asm("ex2.approx.f16x2 %0, %1;" : "=r"(hb) : "r"(hb));
                int col = nt * 8 + 2 * t;
                *(uint32_t*)&sQ[prow0 + col] = ha;
                *(uint32_t*)&sQ[prow1 + col] = hb;
            }

            #pragma unroll
            for (int nt = 0; nt < 8; nt++) {
                accO[nt][0] *= c0; accO[nt][1] *= c0;
                accO[nt][2] *= c1; accO[nt][3] *= c1;
            }
            lacc[0] *= c0; lacc[1] *= c0;
            lacc[2] *= c1; lacc[3] *= c1;
            __syncwarp();

            #pragma unroll
            for (int kc = 0; kc < 4; kc++) {
                uint32_t aP[4];
                {
                    int row = wm + l15;
                    int u   = kc * 2 + lh;
                    ldsm4(aP[0], aP[1], aP[2], aP[3],
                          qB + (uint32_t)(row * HPAD + u * 8) * 2u);
                }
                mma_f16(lacc, aP[0], aP[1], aP[2], aP[3], ONES16, ONES16);
                uint32_t bV[2][2][4];
                #pragma unroll
                for (int kh = 0; kh < 2; kh++)
                    #pragma unroll
                    for (int gb = 0; gb < 2; gb++) {
                        int row = gb * 32 + lane;
                        int u   = kc * 2 + kh;
                        ldsm4(bV[kh][gb][0], bV[kh][gb][1],
                              bV[kh][gb][2], bV[kh][gb][3],
                              vT + (uint32_t)(row * HPAD + u * 8) * 2u);
                    }
                #pragma unroll
                for (int nt = 0; nt < 8; nt++)
                    mma_f16(accO[nt], aP[0], aP[1], aP[2], aP[3],
                            bV[0][nt >> 2][nt & 3], bV[1][nt >> 2][nt & 3]);
            }
        }
        __syncthreads();
    }

    float inv0 = 1.f / lacc[0], inv1 = 1.f / lacc[2];
    __half* o0 = O + ((size_t)(b * T_LEN + r0)) * C_DIM + head * DH;
    __half* o1 = O + ((size_t)(b * T_LEN + r1)) * C_DIM + head * DH;
    #pragma unroll
    for (int nt = 0; nt < 8; nt++) {
        int col = nt * 8 + 2 * t;
        __half2 h0 = __floats2half2_rn(accO[nt][0] * inv0, accO[nt][1] * inv0);
        __half2 h1 = __floats2half2_rn(accO[nt][2] * inv1, accO[nt][3] * inv1);
        *(uint32_t*)(o0 + col) = *(uint32_t*)&h0;
        *(uint32_t*)(o1 + col) = *(uint32_t*)&h1;
    }
}

// ---------------- launch ----------------------------------------------------
extern "C" void kernel_launch(void* const* d_in, const int* in_sizes, int n_in,
                              void* d_out, int out_size) {
    const float* x      = (const float*)d_in[0];
    const float* w_qkv  = (const float*)d_in[1];
    const float* w_proj = (const float*)d_in[2];
    const float* g1     = (const float*)d_in[3];
    const float* g2     = (const float*)d_in[4];
    const float* w1     = (const float*)d_in[5];
    const float* w2     = (const float*)d_in[6];
    const float* w3     = (const float*)d_in[7];
    float* out = (float*)d_out;

    __half *p_h16, *p_qkv16, *p_q16, *p_k16, *p_v16, *p_o16, *p_ff16, *p_w16;
    float  *p_x1;
    cudaGetSymbolAddress((void**)&p_h16,   g_h16);
    cudaGetSymbolAddress((void**)&p_qkv16, g_qkv16);
    cudaGetSymbolAddress((void**)&p_q16,   g_q16);
    cudaGetSymbolAddress((void**)&p_k16,   g_k16);
    cudaGetSymbolAddress((void**)&p_v16,   g_v16);
    cudaGetSymbolAddress((void**)&p_o16,   g_o16);
    cudaGetSymbolAddress((void**)&p_x1,    g_x1);
    cudaGetSymbolAddress((void**)&p_ff16,  g_ff16);
    cudaGetSymbolAddress((void**)&p_w16,   g_w16);

    __half* w_qkv16  = p_w16;
    __half* w_proj16 = w_qkv16  + 3 * C_DIM * C_DIM;
    __half* w116     = w_proj16 + C_DIM * C_DIM;
    __half* w216     = w116     + 4 * C_DIM * C_DIM;
    __half* w316     = w216     + 4 * C_DIM * C_DIM;

    f2h_all_kernel<<<2048, 256>>>(w_qkv, w_proj, w1, w2, w3, p_w16);

    rmsnorm_h_kernel<<<M_TOK, 256>>>(x, g1, p_h16);
    hgemm_kernel<3><<<dim3(3 * C_DIM / 128, M_TOK / 128), 256>>>(
        p_h16, w_qkv16, nullptr, p_qkv16, M_TOK, 3 * C_DIM, C_DIM);
    rope_split_h_kernel<<<(M_TOK * H_NUM * 32) / 256, 256>>>(p_qkv16, p_q16, p_k16);
    vtrans_h_kernel<<<dim3(T_LEN / 64, B_NUM * H_NUM), 256>>>(p_qkv16, p_v16);
    attn_h_kernel<<<dim3(T_LEN / 64, B_NUM * H_NUM), 128>>>(
        p_q16, p_k16, p_v16, p_o16);
    hgemm_kernel<1><<<dim3(C_DIM / 128, M_TOK / 128), 256>>>(
        p_o16, w_proj16, x, p_x1, M_TOK, C_DIM, C_DIM);
    rmsnorm_h_kernel<<<M_TOK, 256>>>(p_x1, g2, p_h16);
    // fused ffn gate: ff = silu(h2@w1^T) * (h2@w3^T)
    ffgate_kernel<<<dim3(FF_DIM / 64, M_TOK / 128), 256>>>(
        p_h16, w116, w316, p_ff16, M_TOK, FF_DIM, C_DIM);
    hgemm_kernel<1><<<dim3(C_DIM / 128, M_TOK / 128), 256>>>(
        p_ff16, w216, p_x1, out, M_TOK, C_DIM, FF_DIM);
}

// round 17
// speedup vs baseline: 1.0997x; 1.0009x over previous
#include <cuda_runtime.h>
#include <cuda_fp16.h>
#include <math.h>
#include <stdint.h>

#define C_DIM   1024
#define H_NUM   16
#define DH      64
#define FF_DIM  4096
#define B_NUM   2
#define T_LEN   2048
#define M_TOK   4096   // B*T

// ---------------- scratch (device globals; no allocation allowed) ----------
__device__ __half g_h16 [M_TOK * C_DIM];       // rmsnorm out (fp16)
__device__ __half g_qkv16[M_TOK * 3 * C_DIM];  // qkv (fp16)
__device__ __half g_q16 [M_TOK * C_DIM];       // [B,H,T,dh] (pre-scaled fp16)
__device__ __half g_k16 [M_TOK * C_DIM];       // [B,H,T,dh] fp16
__device__ __half g_v16 [M_TOK * C_DIM];       // [B,H,dh,T] fp16 (transposed)
__device__ __half g_o16 [M_TOK * C_DIM];       // attention out (fp16)
__device__ float  g_x1  [M_TOK * C_DIM];
__device__ __half g_ff16[M_TOK * FF_DIM];      // silu(a)*b (fp16)
__device__ __half g_w16 [16 * C_DIM * C_DIM];  // all weights fp16 (16M halves)
__device__ float2 g_rot [T_LEN * 32];          // (cos,sin) per (t, pair)

// ---------------- helpers ----------------------------------------------------
__device__ __forceinline__ void mma_f16(float c[4],
                                        uint32_t a0, uint32_t a1, uint32_t a2, uint32_t a3,
                                        uint32_t b0, uint32_t b1) {
    asm volatile(
        "mma.sync.aligned.m16n8k16.row.col.f32.f16.f16.f32 "
        "{%0,%1,%2,%3}, {%4,%5,%6,%7}, {%8,%9}, {%0,%1,%2,%3};\n"
        : "+f"(c[0]), "+f"(c[1]), "+f"(c[2]), "+f"(c[3])
        : "r"(a0), "r"(a1), "r"(a2), "r"(a3), "r"(b0), "r"(b1));
}
__device__ __forceinline__ void ldsm4(uint32_t& r0, uint32_t& r1,
                                      uint32_t& r2, uint32_t& r3, uint32_t addr) {
    asm volatile("ldmatrix.sync.aligned.m8n8.x4.shared.b16 {%0,%1,%2,%3}, [%4];"
                 : "=r"(r0), "=r"(r1), "=r"(r2), "=r"(r3) : "r"(addr));
}
__device__ __forceinline__ void cp16(uint32_t dst, const void* src) {
    asm volatile("cp.async.cg.shared.global [%0], [%1], 16;" :: "r"(dst), "l"(src));
}

// ---------------- RoPE table: (cos,sin) for (t 0..2047, i 0..31) ------------
__global__ void rope_table_kernel(float2* __restrict__ rot) {
    int idx = blockIdx.x * blockDim.x + threadIdx.x;   // < 65536
    int t = idx >> 5, i = idx & 31;
    float freq = expf(-(2.0f * (float)i) * (1.0f / 64.0f) * 9.210340371976184f);
    float s, c;
    sincosf((float)t * freq, &s, &c);
    rot[idx] = make_float2(c, s);
}

// ---------------- fused fp32 -> fp16 weight convert (single launch) ---------
__global__ void f2h_all_kernel(const float* __restrict__ w_qkv,
                               const float* __restrict__ w_proj,
                               const float* __restrict__ w1,
                               const float* __restrict__ w2,
                               const float* __restrict__ w3,
                               __half* __restrict__ out) {
    int unit = blockIdx.x >> 7;
    const float* src;
    if (unit < 3)       src = w_qkv  + ((size_t)unit << 20);
    else if (unit < 4)  src = w_proj;
    else if (unit < 8)  src = w1 + ((size_t)(unit - 4) << 20);
    else if (unit < 12) src = w2 + ((size_t)(unit - 8) << 20);
    else                src = w3 + ((size_t)(unit - 12) << 20);
    __half* dst = out + ((size_t)unit << 20);

    size_t local = (size_t)(blockIdx.x & 127) * 8192 + threadIdx.x * 8;
    #pragma unroll
    for (int j = 0; j < 4; j++) {
        size_t idx = local + (size_t)j * 2048;
        float4 a = *(const float4*)(src + idx);
        float4 b = *(const float4*)(src + idx + 4);
        __half2 h0 = __floats2half2_rn(a.x, a.y);
        __half2 h1 = __floats2half2_rn(a.z, a.w);
        __half2 h2 = __floats2half2_rn(b.x, b.y);
        __half2 h3 = __floats2half2_rn(b.z, b.w);
        uint4 u;
        u.x = *(uint32_t*)&h0; u.y = *(uint32_t*)&h1;
        u.z = *(uint32_t*)&h2; u.w = *(uint32_t*)&h3;
        *(uint4*)(dst + idx) = u;
    }
}

// ---------------- RMSNorm -> fp16 --------------------------------------------
__global__ void rmsnorm_h_kernel(const float* __restrict__ x,
                                 const float* __restrict__ g,
                                 __half* __restrict__ y) {
    int row = blockIdx.x;
    int tid = threadIdx.x;
    const float4* xr = (const float4*)(x + (size_t)row * C_DIM);
    const float4* gr = (const float4*)g;

    float4 xv = xr[tid];
    float ss = xv.x*xv.x + xv.y*xv.y + xv.z*xv.z + xv.w*xv.w;
    #pragma unroll
    for (int off = 16; off > 0; off >>= 1)
        ss += __shfl_xor_sync(0xffffffffu, ss, off);
    __shared__ float red[8];
    if ((tid & 31) == 0) red[tid >> 5] = ss;
    __syncthreads();
    float tot = 0.f;
    #pragma unroll
    for (int i = 0; i < 8; i++) tot += red[i];
    float inv = rsqrtf(tot * (1.0f / C_DIM) + 1e-5f);

    float4 gv = gr[tid];
    __half2 h0 = __floats2half2_rn(xv.x * gv.x * inv, xv.y * gv.y * inv);
    __half2 h1 = __floats2half2_rn(xv.z * gv.z * inv, xv.w * gv.w * inv);
    uint2 u;
    u.x = *(uint32_t*)&h0; u.y = *(uint32_t*)&h1;
    *(uint2*)(y + (size_t)row * C_DIM + tid * 4) = u;
}

// ---------------- fp16 tensor-core GEMM (k32, 3-stage cp.async) -------------
// MODE 0: fp32 out   MODE 1: fp32 out + fp32 X residual   MODE 3: fp16 out
#define GST 3
template <int MODE>
__global__ __launch_bounds__(256, 2)
void hgemm_kernel(const __half* __restrict__ A, const __half* __restrict__ W,
                  const void* X, void* Cout, int M, int N, int K) {
    __shared__ __align__(16) __half sA[GST][128 * 32];
    __shared__ __align__(16) __half sB[GST][128 * 32];

    int tid  = threadIdx.x;
    int bm   = blockIdx.y * 128;
    int bn   = blockIdx.x * 128;
    int warp = tid >> 5;
    int lane = tid & 31;
    int wm   = (warp >> 1) * 32;
    int wn   = (warp & 1) * 64;

    uint32_t dstOff[2];
    int srow[2], su[2];
    #pragma unroll
    for (int j = 0; j < 2; j++) {
        int idx = tid + 256 * j;
        int row = idx >> 2, u = idx & 3;
        int uz  = u ^ ((row >> 1) & 3);
        dstOff[j] = (uint32_t)(row * 32 + uz * 8) * 2u;
        srow[j] = row; su[j] = u;
    }

    uint32_t aBase = (uint32_t)__cvta_generic_to_shared(&sA[0][0]);
    uint32_t bBase = (uint32_t)__cvta_generic_to_shared(&sB[0][0]);

    int l15 = lane & 15, lh = lane >> 4;
    uint32_t offA[2][2];
    #pragma unroll
    for (int q = 0; q < 2; q++)
        #pragma unroll
        for (int mt = 0; mt < 2; mt++) {
            int row = wm + mt * 16 + l15;
            int u   = 2 * q + lh;
            int uz  = u ^ ((row >> 1) & 3);
            offA[q][mt] = (uint32_t)(row * 32 + uz * 8) * 2u;
        }
    uint32_t offB[2][2][2];
    #pragma unroll
    for (int q = 0; q < 2; q++)
        #pragma unroll
        for (int kh = 0; kh < 2; kh++)
            #pragma unroll
            for (int gb = 0; gb < 2; gb++) {
                int row = wn + gb * 32 + lane;
                int u   = 2 * q + kh;
                int uz  = u ^ ((row >> 1) & 3);
                offB[q][kh][gb] = (uint32_t)(row * 32 + uz * 8) * 2u;
            }

    float acc[2][8][4];
    #pragma unroll
    for (int mt = 0; mt < 2; mt++)
        #pragma unroll
        for (int nt = 0; nt < 8; nt++)
            #pragma unroll
            for (int e = 0; e < 4; e++) acc[mt][nt][e] = 0.f;

    int NC = K >> 5;

    #pragma unroll
    for (int s = 0; s < 2; s++) {
        #pragma unroll
        for (int j = 0; j < 2; j++) {
            cp16(aBase + s * 8192u + dstOff[j],
                 A + (size_t)(bm + srow[j]) * K + s * 32 + su[j] * 8);
            cp16(bBase + s * 8192u + dstOff[j],
                 W + (size_t)(bn + srow[j]) * K + s * 32 + su[j] * 8);
        }
        asm volatile("cp.async.commit_group;" ::: "memory");
    }

    int st = 0, sn = 2;
    for (int ck = 0; ck < NC; ck++) {
        asm volatile("cp.async.wait_group 1;" ::: "memory");
        __syncthreads();

        uint32_t tA = aBase + st * 8192u;
        uint32_t tB = bBase + st * 8192u;
        #pragma unroll
        for (int q = 0; q < 2; q++) {
            uint32_t aR[2][4], bR[2][2][4];
            ldsm4(aR[0][0], aR[0][1], aR[0][2], aR[0][3], tA + offA[q][0]);
            ldsm4(aR[1][0], aR[1][1], aR[1][2], aR[1][3], tA + offA[q][1]);
            #pragma unroll
            for (int kh = 0; kh < 2; kh++)
                #pragma unroll
                for (int gb = 0; gb < 2; gb++)
                    ldsm4(bR[kh][gb][0], bR[kh][gb][1], bR[kh][gb][2], bR[kh][gb][3],
                          tB + offB[q][kh][gb]);
            #pragma unroll
            for (int mt = 0; mt < 2; mt++)
                #pragma unroll
                for (int nt = 0; nt < 8; nt++)
                    mma_f16(acc[mt][nt],
                            aR[mt][0], aR[mt][1], aR[mt][2], aR[mt][3],
                            bR[0][nt >> 2][nt & 3], bR[1][nt >> 2][nt & 3]);
        }

        int cn = ck + 2;
        if (cn < NC) {
            uint32_t nA = aBase + sn * 8192u;
            uint32_t nB = bBase + sn * 8192u;
            #pragma unroll
            for (int j = 0; j < 2; j++) {
                cp16(nA + dstOff[j],
                     A + (size_t)(bm + srow[j]) * K + cn * 32 + su[j] * 8);
                cp16(nB + dstOff[j],
                     W + (size_t)(bn + srow[j]) * K + cn * 32 + su[j] * 8);
            }
        }
        asm volatile("cp.async.commit_group;" ::: "memory");

        st = (st + 1 == GST) ? 0 : st + 1;
        sn = (sn + 1 == GST) ? 0 : sn + 1;
    }

    int g = lane >> 2;
    int t = lane & 3;
    #pragma unroll
    for (int mt = 0; mt < 2; mt++) {
        #pragma unroll
        for (int half = 0; half < 2; half++) {
            int row = bm + wm + mt * 16 + half * 8 + g;
            #pragma unroll
            for (int nt = 0; nt < 8; nt++) {
                int col = bn + wn + nt * 8 + 2 * t;
                float2 v;
                v.x = acc[mt][nt][half * 2 + 0];
                v.y = acc[mt][nt][half * 2 + 1];
                if (MODE == 1) {
                    float2 xv = *(const float2*)((const float*)X +
                                                 (size_t)row * N + col);
                    v.x += xv.x; v.y += xv.y;
                }
                if (MODE == 3) {
                    __half2 hv = __floats2half2_rn(v.x, v.y);
                    *(uint32_t*)((__half*)Cout + (size_t)row * N + col) =
                        *(uint32_t*)&hv;
                } else {
                    *(float2*)((float*)Cout + (size_t)row * N + col) = v;
                }
            }
        }
    }
}

// ---------------- fused FFN gate: ff = silu(h@w1^T) * (h@w3^T) --------------
__global__ __launch_bounds__(256, 2)
void ffgate_kernel(const __half* __restrict__ A, const __half* __restrict__ W1,
                   const __half* __restrict__ W3, __half* __restrict__ Cout,
                   int M, int N, int K) {
    __shared__ __align__(16) char smemraw[49152];
    __half* sA = (__half*)smemraw;                 // 3 x 8KB
    uint32_t aBase  = (uint32_t)__cvta_generic_to_shared(sA);
    uint32_t b1Base = aBase + 24576u;
    uint32_t b2Base = aBase + 36864u;

    int tid  = threadIdx.x;
    int bm   = blockIdx.y * 128;
    int bn   = blockIdx.x * 64;
    int warp = tid >> 5;
    int lane = tid & 31;
    int halfw = warp >> 2;
    int wm    = (warp & 3) * 32;

    uint32_t dstOffA[2];
    int arow[2], au[2];
    #pragma unroll
    for (int j = 0; j < 2; j++) {
        int idx = tid + 256 * j;
        int row = idx >> 2, u = idx & 3;
        int uz  = u ^ ((row >> 1) & 3);
        dstOffA[j] = (uint32_t)(row * 32 + uz * 8) * 2u;
        arow[j] = row; au[j] = u;
    }
    int brow = tid >> 2, bu = tid & 3;
    uint32_t dstOffB = (uint32_t)(brow * 32 + (bu ^ ((brow >> 1) & 3)) * 8) * 2u;

    int l15 = lane & 15, lh = lane >> 4;
    uint32_t offA[2][2];
    #pragma unroll
    for (int q = 0; q < 2; q++)
        #pragma unroll
        for (int mt = 0; mt < 2; mt++) {
            int row = wm + mt * 16 + l15;
            int u   = 2 * q + lh;
            int uz  = u ^ ((row >> 1) & 3);
            offA[q][mt] = (uint32_t)(row * 32 + uz * 8) * 2u;
        }
    uint32_t offB[2][2][2];
    #pragma unroll
    for (int q = 0; q < 2; q++)
        #pragma unroll
        for (int kh = 0; kh < 2; kh++)
            #pragma unroll
            for (int gb = 0; gb < 2; gb++) {
                int row = gb * 32 + lane;
                int u   = 2 * q + kh;
                int uz  = u ^ ((row >> 1) & 3);
                offB[q][kh][gb] = (uint32_t)(row * 32 + uz * 8) * 2u;
            }
    uint32_t bSel = halfw ? b2Base : b1Base;

    float acc[2][8][4];
    #pragma unroll
    for (int mt = 0; mt < 2; mt++)
        #pragma unroll
        for (int nt = 0; nt < 8; nt++)
            #pragma unroll
            for (int e = 0; e < 4; e++) acc[mt][nt][e] = 0.f;

    int NC = K >> 5;

    #pragma unroll
    for (int s = 0; s < 2; s++) {
        #pragma unroll
        for (int j = 0; j < 2; j++)
            cp16(aBase + s * 8192u + dstOffA[j],
                 A + (size_t)(bm + arow[j]) * K + s * 32 + au[j] * 8);
        cp16(b1Base + s * 4096u + dstOffB,
             W1 + (size_t)(bn + brow) * K + s * 32 + bu * 8);
        cp16(b2Base + s * 4096u + dstOffB,
             W3 + (size_t)(bn + brow) * K + s * 32 + bu * 8);
        asm volatile("cp.async.commit_group;" ::: "memory");
    }

    int st = 0, sn = 2;
    for (int ck = 0; ck < NC; ck++) {
        asm volatile("cp.async.wait_group 1;" ::: "memory");
        __syncthreads();

        uint32_t tA = aBase + st * 8192u;
        uint32_t tB = bSel + st * 4096u;
        #pragma unroll
        for (int q = 0; q < 2; q++) {
            uint32_t aR[2][4], bR[2][2][4];
            ldsm4(aR[0][0], aR[0][1], aR[0][2], aR[0][3], tA + offA[q][0]);
            ldsm4(aR[1][0], aR[1][1], aR[1][2], aR[1][3], tA + offA[q][1]);
            #pragma unroll
            for (int kh = 0; kh < 2; kh++)
                #pragma unroll
                for (int gb = 0; gb < 2; gb++)
                    ldsm4(bR[kh][gb][0], bR[kh][gb][1], bR[kh][gb][2], bR[kh][gb][3],
                          tB + offB[q][kh][gb]);
            #pragma unroll
            for (int mt = 0; mt < 2; mt++)
                #pragma unroll
                for (int nt = 0; nt < 8; nt++)
                    mma_f16(acc[mt][nt],
                            aR[mt][0], aR[mt][1], aR[mt][2], aR[mt][3],
                            bR[0][nt >> 2][nt & 3], bR[1][nt >> 2][nt & 3]);
        }

        int cn = ck + 2;
        if (cn < NC) {
            uint32_t nst = (uint32_t)sn;
            #pragma unroll
            for (int j = 0; j < 2; j++)
                cp16(aBase + nst * 8192u + dstOffA[j],
                     A + (size_t)(bm + arow[j]) * K + cn * 32 + au[j] * 8);
            cp16(b1Base + nst * 4096u + dstOffB,
                 W1 + (size_t)(bn + brow) * K + cn * 32 + bu * 8);
            cp16(b2Base + nst * 4096u + dstOffB,
                 W3 + (size_t)(bn + brow) * K + cn * 32 + bu * 8);
        }
        asm volatile("cp.async.commit_group;" ::: "memory");

        st = (st + 1 == GST) ? 0 : st + 1;
        sn = (sn + 1 == GST) ? 0 : sn + 1;
    }

    asm volatile("cp.async.wait_group 0;" ::: "memory");
    __syncthreads();
    float* sX = (float*)smemraw;

    int g = lane >> 2;
    int t = lane & 3;
    if (halfw == 0) {
        #pragma unroll
        for (int mt = 0; mt < 2; mt++)
            #pragma unroll
            for (int hh = 0; hh < 2; hh++) {
                int row = wm + mt * 16 + hh * 8 + g;
                #pragma unroll
                for (int nt = 0; nt < 8; nt++) {
                    int col = nt * 8 + 2 * t;
                    float ax = acc[mt][nt][hh * 2 + 0];
                    float ay = acc[mt][nt][hh * 2 + 1];
                    float2 v;
                    v.x = ax / (1.f + expf(-ax));
                    v.y = ay / (1.f + expf(-ay));
                    *(float2*)&sX[row * 64 + col] = v;
                }
            }
    }
    __syncthreads();
    if (halfw == 1) {
        #pragma unroll
        for (int mt = 0; mt < 2; mt++)
            #pragma unroll
            for (int hh = 0; hh < 2; hh++) {
                int row = wm + mt * 16 + hh * 8 + g;
                #pragma unroll
                for (int nt = 0; nt < 8; nt++) {
                    int col = nt * 8 + 2 * t;
                    float2 sa = *(const float2*)&sX[row * 64 + col];
                    __half2 hv = __floats2half2_rn(
                        acc[mt][nt][hh * 2 + 0] * sa.x,
                        acc[mt][nt][hh * 2 + 1] * sa.y);
                    *(uint32_t*)(Cout + (size_t)(bm + row) * N + bn + col) =
                        *(uint32_t*)&hv;
                }
            }
    }
}

// ---------------- RoPE (table) + split qkv(fp16) -> q,k fp16 ----------------
#define Q_SCALE (0.125f * 1.44269504088896f)   // 1/sqrt(64) * log2(e)
__global__ void rope_split_h_kernel(const __half* __restrict__ qkv,
                                    const float2* __restrict__ rot,
                                    __half* __restrict__ q,
                                    __half* __restrict__ k) {
    int idx = blockIdx.x * blockDim.x + threadIdx.x;
    int i = idx & 31;
    int h = (idx >> 5) & 15;
    int m = idx >> 9;
    int b = m >> 11;
    int t = m & 2047;

    const __half* base = qkv + (size_t)m * (3 * C_DIM) + h * DH + 2 * i;
    __half2 qv = *(const __half2*)(base);
    __half2 kv = *(const __half2*)(base + C_DIM);
    float q1 = __low2float(qv), q2 = __high2float(qv);
    float k1 = __low2float(kv), k2 = __high2float(kv);

    float2 cs = rot[t * 32 + i];
    float c = cs.x, s = cs.y;

    size_t o = ((size_t)(b * H_NUM + h) * T_LEN + t) * DH + 2 * i;
    __half2 qh = __floats2half2_rn((q1 * c - q2 * s) * Q_SCALE,
                                   (q1 * s + q2 * c) * Q_SCALE);
    __half2 kh = __floats2half2_rn(k1 * c - k2 * s, k1 * s + k2 * c);
    *(uint32_t*)(q + o) = *(uint32_t*)&qh;
    *(uint32_t*)(k + o) = *(uint32_t*)&kh;
}

// ---------------- V transpose: qkv(fp16) v-section -> [B,H,dh,T] fp16 -------
__global__ void vtrans_h_kernel(const __half* __restrict__ qkv,
                                __half* __restrict__ vt) {
    __shared__ __half s[64][68];
    int bh = blockIdx.y;
    int b  = bh >> 4;
    int h  = bh & 15;
    int t0 = blockIdx.x * 64;
    int tid = threadIdx.x;

    for (int idx = tid; idx < 64 * 16; idx += 256) {
        int tok = idx >> 4, u = idx & 15;
        uint2 hv = *(const uint2*)(qkv + (size_t)(b * T_LEN + t0 + tok) * (3 * C_DIM)
                                   + 2 * C_DIM + h * DH + u * 4);
        *(uint2*)&s[tok][u * 4] = hv;
    }
    __syncthreads();
    for (int idx = tid; idx < 64 * 32; idx += 256) {
        int d = idx >> 5, tp = idx & 31;
        __half2 hv = __halves2half2(s[2 * tp][d], s[2 * tp + 1][d]);
        *(uint32_t*)(vt + ((size_t)bh * DH + d) * T_LEN + t0 + 2 * tp) =
            *(uint32_t*)&hv;
    }
}

// ---------------- fp16 causal flash attention (heavy-first ordering) --------
#define HPAD 72
#define ONES16 0x3C003C00u
#define KV_TILE (64 * HPAD)
__global__ __launch_bounds__(128)
void attn_h_kernel(const __half* __restrict__ Q,
                   const __half* __restrict__ Kg,
                   const __half* __restrict__ Vt,
                   __half* __restrict__ O) {
    __shared__ __align__(16) __half sQ[64 * HPAD];     // later: P
    __shared__ __align__(16) __half sK[2][KV_TILE];
    __shared__ __align__(16) __half sV[2][KV_TILE];

    int bh   = blockIdx.y;
    int b    = bh >> 4;
    int head = bh & 15;
    // heavy-first: largest q0 (most K-tiles) scheduled earliest
    int q0   = (gridDim.x - 1 - blockIdx.x) * 64;
    int tid  = threadIdx.x;
    int warp = tid >> 5;
    int lane = tid & 31;
    int wm   = warp * 16;
    int g    = lane >> 2;
    int t    = lane & 3;
    int l15  = lane & 15;
    int lh   = lane >> 4;

    uint32_t qB = (uint32_t)__cvta_generic_to_shared(sQ);
    uint32_t kB = (uint32_t)__cvta_generic_to_shared(&sK[0][0]);
    uint32_t vB = (uint32_t)__cvta_generic_to_shared(&sV[0][0]);

    const __half* kg0 = Kg + (size_t)bh * T_LEN * DH;
    const __half* vg0 = Vt + (size_t)bh * DH * T_LEN;

    int cr[4], cu[4];
    uint32_t cOff[4];
    #pragma unroll
    for (int j = 0; j < 4; j++) {
        int idx = tid + 128 * j;
        cr[j] = idx >> 3; cu[j] = idx & 7;
        cOff[j] = (uint32_t)(cr[j] * HPAD + cu[j] * 8) * 2u;
    }

    const __half* qg = Q + ((size_t)bh * T_LEN + q0) * DH;
    #pragma unroll
    for (int idx = tid; idx < 512; idx += 128) {
        int r = idx >> 3, u = idx & 7;
        *(uint4*)&sQ[r * HPAD + u * 8] = *(const uint4*)(qg + r * DH + u * 8);
    }

    #pragma unroll
    for (int j = 0; j < 4; j++) {
        cp16(kB + cOff[j], kg0 + (size_t)cr[j] * DH + cu[j] * 8);
        cp16(vB + cOff[j], vg0 + (size_t)cr[j] * T_LEN + cu[j] * 8);
    }
    asm volatile("cp.async.commit_group;" ::: "memory");
    __syncthreads();

    uint32_t qf[4][4];
    #pragma unroll
    for (int kc = 0; kc < 4; kc++) {
        int row = wm + l15;
        int u   = kc * 2 + lh;
        ldsm4(qf[kc][0], qf[kc][1], qf[kc][2], qf[kc][3],
              qB + (uint32_t)(row * HPAD + u * 8) * 2u);
    }
    __syncthreads();   // sQ now reusable as P

    float accO[8][4];
    #pragma unroll
    for (int nt = 0; nt < 8; nt++)
        #pragma unroll
        for (int e = 0; e < 4; e++) accO[nt][e] = 0.f;
    float lacc[4] = {0.f, 0.f, 0.f, 0.f};
    float m0 = -1e30f, m1 = -1e30f;

    int r0 = q0 + wm + g;
    int r1 = r0 + 8;
    int prow0 = (wm + g) * HPAD;
    int prow1 = (wm + g + 8) * HPAD;

    int ntiles = q0 / 64 + 1;
    for (int kt = 0; kt < ntiles; kt++) {
        int st = kt & 1;
        bool more = (kt + 1) < ntiles;
        if (more) {
            int ks1 = (kt + 1) * 64;
            uint32_t kS = kB + (st ^ 1) * (KV_TILE * 2);
            uint32_t vS = vB + (st ^ 1) * (KV_TILE * 2);
            const __half* kbase = kg0 + (size_t)ks1 * DH;
            const __half* vbase = vg0 + ks1;
            #pragma unroll
            for (int j = 0; j < 4; j++) {
                cp16(kS + cOff[j], kbase + (size_t)cr[j] * DH + cu[j] * 8);
                cp16(vS + cOff[j], vbase + (size_t)cr[j] * T_LEN + cu[j] * 8);
            }
        }
        asm volatile("cp.async.commit_group;" ::: "memory");
        if (more)
            asm volatile("cp.async.wait_group 1;" ::: "memory");
        else
            asm volatile("cp.async.wait_group 0;" ::: "memory");
        __syncthreads();

        int ks = kt * 64;
        uint32_t kT = kB + st * (KV_TILE * 2);
        uint32_t vT = vB + st * (KV_TILE * 2);

        if (ks <= q0 + wm + 15) {
            float s[8][4];
            #pragma unroll
            for (int nt = 0; nt < 8; nt++)
                #pragma unroll
                for (int e = 0; e < 4; e++) s[nt][e] = 0.f;

            #pragma unroll
            for (int kc = 0; kc < 4; kc++) {
                uint32_t bR[2][2][4];
                #pragma unroll
                for (int kh = 0; kh < 2; kh++)
                    #pragma unroll
                    for (int gb = 0; gb < 2; gb++) {
                        int row = gb * 32 + lane;
                        int u   = kc * 2 + kh;
                        ldsm4(bR[kh][gb][0], bR[kh][gb][1],
                              bR[kh][gb][2], bR[kh][gb][3],
                              kT + (uint32_t)(row * HPAD + u * 8) * 2u);
                    }
                #pragma unroll
                for (int nt = 0; nt < 8; nt++)
                    mma_f16(s[nt], qf[kc][0], qf[kc][1], qf[kc][2], qf[kc][3],
                            bR[0][nt >> 2][nt & 3], bR[1][nt >> 2][nt & 3]);
            }

            if (ks + 63 > q0 + wm) {
                #pragma unroll
                for (int nt = 0; nt < 8; nt++) {
                    int kc = ks + nt * 8 + 2 * t;
                    if (kc     > r0) s[nt][0] = -1e30f;
                    if (kc + 1 > r0) s[nt][1] = -1e30f;
                    if (kc     > r1) s[nt][2] = -1e30f;
                    if (kc + 1 > r1) s[nt][3] = -1e30f;
                }
            }

            float tm0 = -1e30f, tm1 = -1e30f;
            #pragma unroll
            for (int nt = 0; nt < 8; nt++) {
                tm0 = fmaxf(tm0, fmaxf(s[nt][0], s[nt][1]));
                tm1 = fmaxf(tm1, fmaxf(s[nt][2], s[nt][3]));
            }
            tm0 = fmaxf(tm0, __shfl_xor_sync(0xffffffffu, tm0, 1));
            tm0 = fmaxf(tm0, __shfl_xor_sync(0xffffffffu, tm0, 2));
            tm1 = fmaxf(tm1, __shfl_xor_sync(0xffffffffu, tm1, 1));
            tm1 = fmaxf(tm1, __shfl_xor_sync(0xffffffffu, tm1, 2));

            float mn0 = fmaxf(m0, tm0), mn1 = fmaxf(m1, tm1);
            float c0 = exp2f(m0 - mn0), c1 = exp2f(m1 - mn1);
            m0 = mn0; m1 = mn1;

            #pragma unroll
            for (int nt = 0; nt < 8; nt++) {
                uint32_t ha, hb;
                asm("cvt.rn.f16x2.f32 %0, %1, %2;" : "=r"(ha)
                    : "f"(s[nt][1] - mn0), "f"(s[nt][0] - mn0));
                asm("cvt.rn.f16x2.f32 %0, %1, %2;" : "=r"(hb)
                    : "f"(s[nt][3] - mn1), "f"(s[nt][2] - mn1));
                asm("ex2.approx.f16x2 %0, %1;" : "=r"(ha) : "r"(ha));
                asm("ex2.approx.f16x2 %0, %1;" : "=r"(hb) : "r"(hb));
                int col = nt * 8 + 2 * t;
                *(uint32_t*)&sQ[prow0 + col] = ha;
                *(uint32_t*)&sQ[prow1 + col] = hb;
            }

            #pragma unroll
            for (int nt = 0; nt < 8; nt++) {
                accO[nt][0] *= c0; accO[nt][1] *= c0;
                accO[nt][2] *= c1; accO[nt][3] *= c1;
            }
            lacc[0] *= c0; lacc[1] *= c0;
            lacc[2] *= c1; lacc[3] *= c1;
            __syncwarp();

            #pragma unroll
            for (int kc = 0; kc < 4; kc++) {
                uint32_t aP[4];
                {
                    int row = wm + l15;
                    int u   = kc * 2 + lh;
                    ldsm4(aP[0], aP[1], aP[2], aP[3],
                          qB + (uint32_t)(row * HPAD + u * 8) * 2u);
                }
                mma_f16(lacc, aP[0], aP[1], aP[2], aP[3], ONES16, ONES16);
                uint32_t bV[2][2][4];
                #pragma unroll
                for (int kh = 0; kh < 2; kh++)
                    #pragma unroll
                    for (int gb = 0; gb < 2; gb++) {
                        int row = gb * 32 + lane;
                        int u   = kc * 2 + kh;
                        ldsm4(bV[kh][gb][0], bV[kh][gb][1],
                              bV[kh][gb][2], bV[kh][gb][3],
                              vT + (uint32_t)(row * HPAD + u * 8) * 2u);
                    }
                #pragma unroll
                for (int nt = 0; nt < 8; nt++)
                    mma_f16(accO[nt], aP[0], aP[1], aP[2], aP[3],
                            bV[0][nt >> 2][nt & 3], bV[1][nt >> 2][nt & 3]);
            }
        }
        __syncthreads();
    }

    float inv0 = 1.f / lacc[0], inv1 = 1.f / lacc[2];
    __half* o0 = O + ((size_t)(b * T_LEN + r0)) * C_DIM + head * DH;
    __half* o1 = O + ((size_t)(b * T_LEN + r1)) * C_DIM + head * DH;
    #pragma unroll
    for (int nt = 0; nt < 8; nt++) {
        int col = nt * 8 + 2 * t;
        __half2 h0 = __floats2half2_rn(accO[nt][0] * inv0, accO[nt][1] * inv0);
        __half2 h1 = __floats2half2_rn(accO[nt][2] * inv1, accO[nt][3] * inv1);
        *(uint32_t*)(o0 + col) = *(uint32_t*)&h0;
        *(uint32_t*)(o1 + col) = *(uint32_t*)&h1;
    }
}

// ---------------- launch ----------------------------------------------------
extern "C" void kernel_launch(void* const* d_in, const int* in_sizes, int n_in,
                              void* d_out, int out_size) {
    const float* x      = (const float*)d_in[0];
    const float* w_qkv  = (const float*)d_in[1];
    const float* w_proj = (const float*)d_in[2];
    const float* g1     = (const float*)d_in[3];
    const float* g2     = (const float*)d_in[4];
    const float* w1     = (const float*)d_in[5];
    const float* w2     = (const float*)d_in[6];
    const float* w3     = (const float*)d_in[7];
    float* out = (float*)d_out;

    __half *p_h16, *p_qkv16, *p_q16, *p_k16, *p_v16, *p_o16, *p_ff16, *p_w16;
    float  *p_x1;
    float2 *p_rot;
    cudaGetSymbolAddress((void**)&p_h16,   g_h16);
    cudaGetSymbolAddress((void**)&p_qkv16, g_qkv16);
    cudaGetSymbolAddress((void**)&p_q16,   g_q16);
    cudaGetSymbolAddress((void**)&p_k16,   g_k16);
    cudaGetSymbolAddress((void**)&p_v16,   g_v16);
    cudaGetSymbolAddress((void**)&p_o16,   g_o16);
    cudaGetSymbolAddress((void**)&p_x1,    g_x1);
    cudaGetSymbolAddress((void**)&p_ff16,  g_ff16);
    cudaGetSymbolAddress((void**)&p_w16,   g_w16);
    cudaGetSymbolAddress((void**)&p_rot,   g_rot);

    __half* w_qkv16  = p_w16;
    __half* w_proj16 = w_qkv16  + 3 * C_DIM * C_DIM;
    __half* w116     = w_proj16 + C_DIM * C_DIM;
    __half* w216     = w116     + 4 * C_DIM * C_DIM;
    __half* w316     = w216     + 4 * C_DIM * C_DIM;

    rope_table_kernel<<<256, 256>>>(p_rot);
    f2h_all_kernel<<<2048, 256>>>(w_qkv, w_proj, w1, w2, w3, p_w16);

    rmsnorm_h_kernel<<<M_TOK, 256>>>(x, g1, p_h16);
    hgemm_kernel<3><<<dim3(3 * C_DIM / 128, M_TOK / 128), 256>>>(
        p_h16, w_qkv16, nullptr, p_qkv16, M_TOK, 3 * C_DIM, C_DIM);
    rope_split_h_kernel<<<(M_TOK * H_NUM * 32) / 256, 256>>>(
        p_qkv16, p_rot, p_q16, p_k16);
    vtrans_h_kernel<<<dim3(T_LEN / 64, B_NUM * H_NUM), 256>>>(p_qkv16, p_v16);
    attn_h_kernel<<<dim3(T_LEN / 64, B_NUM * H_NUM), 128>>>(
        p_q16, p_k16, p_v16, p_o16);
    hgemm_kernel<1><<<dim3(C_DIM / 128, M_TOK / 128), 256>>>(
        p_o16, w_proj16, x, p_x1, M_TOK, C_DIM, C_DIM);
    rmsnorm_h_kernel<<<M_TOK, 256>>>(p_x1, g2, p_h16);
    ffgate_kernel<<<dim3(FF_DIM / 64, M_TOK / 128), 256>>>(
        p_h16, w116, w316, p_ff16, M_TOK, FF_DIM, C_DIM);
    hgemm_kernel<1><<<dim3(C_DIM / 128, M_TOK / 128), 256>>>(
        p_ff16, w216, p_x1, out, M_TOK, C_DIM, FF_DIM);
}